// round 2
// baseline (speedup 1.0000x reference)
#include <cuda_runtime.h>

// ---------------- problem constants ----------------
#define NHEADS 16
#define CDIM   512
#define HD     32
#define NTOK   64            // tokens per window (8x8)
#define NWIN   2048          // 8 batches * 16 * 16 windows
#define NROWS  (NWIN * NTOK) // 131072 total tokens

// ---------------- scratch (device globals; allocation-free) ----------------
__device__ float g_q[(size_t)NWIN * NHEADS * NTOK * HD];   // 256 MiB
__device__ float g_k[(size_t)NWIN * NHEADS * NTOK * HD];   // 256 MiB
__device__ float g_v[(size_t)NWIN * NHEADS * NTOK * HD];   // 256 MiB
__device__ float g_ao[(size_t)NROWS * CDIM];               // 256 MiB

// ---------------- helpers ----------------
__device__ __forceinline__ float f2tf(float x) {
    unsigned u;
    asm("cvt.rna.tf32.f32 %0, %1;" : "=r"(u) : "f"(x));
    return __uint_as_float(u);
}

// m16n8k8 tf32 mma, D += A*B (A row-major 16x8, B col-major 8x8)
__device__ __forceinline__ void mma_tf32(float c[4], const float a[4], const float b[2]) {
    asm volatile(
        "mma.sync.aligned.m16n8k8.row.col.f32.tf32.tf32.f32 "
        "{%0,%1,%2,%3},{%4,%5,%6,%7},{%8,%9},{%0,%1,%2,%3};\n"
        : "+f"(c[0]), "+f"(c[1]), "+f"(c[2]), "+f"(c[3])
        : "r"(__float_as_uint(a[0])), "r"(__float_as_uint(a[1])),
          "r"(__float_as_uint(a[2])), "r"(__float_as_uint(a[3])),
          "r"(__float_as_uint(b[0])), "r"(__float_as_uint(b[1])));
}

// token n of window widx -> row index in flat (B*H*W) space
__device__ __forceinline__ long xrow(int widx, int n) {
    int b  = widx >> 8;
    int hy = (widx >> 4) & 15;
    int wx = widx & 15;
    int h  = hy * 8 + (n >> 3);
    int w  = wx * 8 + (n & 7);
    return ((long)((b << 7) + h) << 7) + w;   // (b*128 + h)*128 + w
}

// ---------------- 3xTF32 GEMM (MODE 0: QKV w/ window gather, MODE 1: proj w/ reverse scatter) ----
// Block: 256 threads (8 warps, 2x4 warp grid, 32x32 warp tiles), Mtile=64, Ntile=128, Ktile=32.
// SMEM strides padded (A:36, B:132) for conflict-free fragment loads.
#define GEMM_SMEM_FLOATS 13056   // 2*(64*36) + 2*(32*132)

template <int MODE>
__global__ __launch_bounds__(256) void gemm3x(
    const float* __restrict__ Ain, const float* __restrict__ W,
    const float* __restrict__ bias, float* __restrict__ out)
{
    constexpr int NT  = (MODE == 0) ? 12 : 4;     // N tiles of 128
    constexpr int NLD = (MODE == 0) ? 1536 : 512; // leading dim of W

    extern __shared__ float sm[];
    float* sAh = sm;            // 64 x 36
    float* sAl = sm + 2304;
    float* sBh = sm + 4608;     // 32 x 132
    float* sBl = sm + 8832;

    const float* Ap = (MODE == 0) ? Ain : g_ao;

    const int widx = blockIdx.x;
    const int tid  = threadIdx.x;
    const int wid  = tid >> 5, lane = tid & 31;
    const int g    = lane >> 2, t4 = lane & 3;
    const int wm   = wid & 1,  wn  = wid >> 1;

    // base addresses (in floats) of the two A rows this thread loads
    long arow[2];
#pragma unroll
    for (int i = 0; i < 2; i++) {
        int idx = tid + i * 256;
        int r   = idx >> 3;
        arow[i] = (MODE == 0) ? xrow(widx, r) * 512L : ((long)widx * 64 + r) * 512L;
    }

    for (int nt = 0; nt < NT; ++nt) {
        float acc[2][4][4];
#pragma unroll
        for (int a = 0; a < 2; a++)
#pragma unroll
            for (int b = 0; b < 4; b++)
#pragma unroll
                for (int c = 0; c < 4; c++) acc[a][b][c] = 0.f;

        for (int kt = 0; kt < 16; ++kt) {
            // A tile: 64x32 fp32 = 512 float4, 2 per thread (L2-resident on re-passes)
#pragma unroll
            for (int i = 0; i < 2; i++) {
                int idx = tid + i * 256;
                int r = idx >> 3, c4 = idx & 7;
                float4 v = *reinterpret_cast<const float4*>(Ap + arow[i] + kt * 32 + c4 * 4);
                int sb = r * 36 + c4 * 4;
                float h0 = f2tf(v.x); sAh[sb + 0] = h0; sAl[sb + 0] = f2tf(v.x - h0);
                float h1 = f2tf(v.y); sAh[sb + 1] = h1; sAl[sb + 1] = f2tf(v.y - h1);
                float h2 = f2tf(v.z); sAh[sb + 2] = h2; sAl[sb + 2] = f2tf(v.z - h2);
                float h3 = f2tf(v.w); sAh[sb + 3] = h3; sAl[sb + 3] = f2tf(v.w - h3);
            }
            // B tile: 32x128 fp32 = 1024 float4, 4 per thread (weights are L2-resident)
#pragma unroll
            for (int i = 0; i < 4; i++) {
                int idx = tid + i * 256;
                int k = idx >> 5, c4 = idx & 31;
                float4 v = *reinterpret_cast<const float4*>(
                    W + (size_t)(kt * 32 + k) * NLD + nt * 128 + c4 * 4);
                int sb = k * 132 + c4 * 4;
                float h0 = f2tf(v.x); sBh[sb + 0] = h0; sBl[sb + 0] = f2tf(v.x - h0);
                float h1 = f2tf(v.y); sBh[sb + 1] = h1; sBl[sb + 1] = f2tf(v.y - h1);
                float h2 = f2tf(v.z); sBh[sb + 2] = h2; sBl[sb + 2] = f2tf(v.z - h2);
                float h3 = f2tf(v.w); sBh[sb + 3] = h3; sBl[sb + 3] = f2tf(v.w - h3);
            }
            __syncthreads();

#pragma unroll
            for (int ks = 0; ks < 4; ++ks) {
                float ah[2][4], al[2][4];
#pragma unroll
                for (int mi = 0; mi < 2; mi++) {
                    int r0 = wm * 32 + mi * 16 + g;
                    int c0 = ks * 8 + t4;
                    ah[mi][0] = sAh[r0 * 36 + c0];       ah[mi][1] = sAh[(r0 + 8) * 36 + c0];
                    ah[mi][2] = sAh[r0 * 36 + c0 + 4];   ah[mi][3] = sAh[(r0 + 8) * 36 + c0 + 4];
                    al[mi][0] = sAl[r0 * 36 + c0];       al[mi][1] = sAl[(r0 + 8) * 36 + c0];
                    al[mi][2] = sAl[r0 * 36 + c0 + 4];   al[mi][3] = sAl[(r0 + 8) * 36 + c0 + 4];
                }
                float bh[4][2], bl[4][2];
#pragma unroll
                for (int ni = 0; ni < 4; ni++) {
                    int col = wn * 32 + ni * 8 + g;
                    int kr  = ks * 8 + t4;
                    bh[ni][0] = sBh[kr * 132 + col]; bh[ni][1] = sBh[(kr + 4) * 132 + col];
                    bl[ni][0] = sBl[kr * 132 + col]; bl[ni][1] = sBl[(kr + 4) * 132 + col];
                }
#pragma unroll
                for (int mi = 0; mi < 2; mi++)
#pragma unroll
                    for (int ni = 0; ni < 4; ni++) {
                        mma_tf32(acc[mi][ni], al[mi], bh[ni]);  // lo*hi
                        mma_tf32(acc[mi][ni], ah[mi], bl[ni]);  // hi*lo
                        mma_tf32(acc[mi][ni], ah[mi], bh[ni]);  // hi*hi
                    }
            }
            __syncthreads();
        }

        // epilogue: bias + scatter
#pragma unroll
        for (int mi = 0; mi < 2; mi++)
#pragma unroll
            for (int ni = 0; ni < 4; ni++)
#pragma unroll
                for (int j = 0; j < 4; j++) {
                    int rl = wm * 32 + mi * 16 + g + ((j >> 1) << 3);
                    int cl = wn * 32 + ni * 8 + 2 * t4 + (j & 1);
                    int co = nt * 128 + cl;
                    float v = acc[mi][ni][j] + __ldg(bias + co);
                    if (MODE == 0) {
                        int part = co >> 9, cc = co & 511;
                        int hh = cc >> 5, d = cc & 31;
                        float* dst = (part == 0) ? g_q : ((part == 1) ? g_k : g_v);
                        dst[(((size_t)widx * 16 + hh) * 64 + rl) * 32 + d] = v;
                    } else {
                        out[xrow(widx, rl) * 512L + co] = v;
                    }
                }
    }
}

// ---------------- attention: one block per (window, head), 4 warps x 16 query rows ----
__global__ __launch_bounds__(128) void attn_kernel(const float* __restrict__ tbl) {
    __shared__ float sQ[64 * 36];
    __shared__ float sK[64 * 36];
    __shared__ float sV[64 * 36];
    __shared__ float sP[64 * 68];
    __shared__ float sRcp[64];

    const int bx   = blockIdx.x;
    const int widx = bx >> 4, head = bx & 15;
    const int tid  = threadIdx.x, wid = tid >> 5, lane = tid & 31;
    const int g    = lane >> 2, t4 = lane & 3;
    const size_t base = (size_t)bx * 2048;   // 64 * 32 floats per (win, head)

    // stage Q/K/V (tf32-rounded) into padded SMEM
#pragma unroll
    for (int i = 0; i < 4; i++) {
        int idx = tid + i * 128;            // 512 float4 total
        int r = idx >> 3, c4 = idx & 7;
        int sb = r * 36 + c4 * 4;
        float4 q = *reinterpret_cast<const float4*>(g_q + base + (size_t)idx * 4);
        float4 k = *reinterpret_cast<const float4*>(g_k + base + (size_t)idx * 4);
        float4 v = *reinterpret_cast<const float4*>(g_v + base + (size_t)idx * 4);
        sQ[sb] = f2tf(q.x); sQ[sb + 1] = f2tf(q.y); sQ[sb + 2] = f2tf(q.z); sQ[sb + 3] = f2tf(q.w);
        sK[sb] = f2tf(k.x); sK[sb + 1] = f2tf(k.y); sK[sb + 2] = f2tf(k.z); sK[sb + 3] = f2tf(k.w);
        sV[sb] = f2tf(v.x); sV[sb + 1] = f2tf(v.y); sV[sb + 2] = f2tf(v.z); sV[sb + 3] = f2tf(v.w);
    }
    __syncthreads();

    const int r0 = wid * 16;

    // S = Q K^T  (16x64 per warp)
    float sacc[8][4];
#pragma unroll
    for (int n = 0; n < 8; n++)
#pragma unroll
        for (int j = 0; j < 4; j++) sacc[n][j] = 0.f;

#pragma unroll
    for (int ks = 0; ks < 4; ks++) {
        float a[4];
        int rr = r0 + g, c0 = ks * 8 + t4;
        a[0] = sQ[rr * 36 + c0];     a[1] = sQ[(rr + 8) * 36 + c0];
        a[2] = sQ[rr * 36 + c0 + 4]; a[3] = sQ[(rr + 8) * 36 + c0 + 4];
#pragma unroll
        for (int ni = 0; ni < 8; ni++) {
            float b[2];
            int n = ni * 8 + g;
            b[0] = sK[n * 36 + c0];
            b[1] = sK[n * 36 + c0 + 4];
            mma_tf32(sacc[ni], a, b);
        }
    }

    // scale + relative position bias -> sP (raw logits)
    const float scale = 0.17677669529663687f;  // 32^-0.5
#pragma unroll
    for (int ni = 0; ni < 8; ni++)
#pragma unroll
        for (int j = 0; j < 4; j++) {
            int r = r0 + g + ((j >> 1) << 3);
            int c = ni * 8 + 2 * t4 + (j & 1);
            int idx = ((r >> 3) - (c >> 3) + 7) * 15 + ((r & 7) - (c & 7) + 7);
            sP[r * 68 + c] = sacc[ni][j] * scale + __ldg(tbl + idx * 16 + head);
        }
    __syncwarp();

    // softmax over 64 keys (2 lanes per row); store exp() (tf32) and 1/rowsum
    {
        int r = r0 + (lane >> 1);
        int half = lane & 1;
        float* row = sP + r * 68 + half * 32;
        float m = row[0];
#pragma unroll
        for (int c = 1; c < 32; c++) m = fmaxf(m, row[c]);
        m = fmaxf(m, __shfl_xor_sync(0xffffffffu, m, 1));
        float s = 0.f;
#pragma unroll
        for (int c = 0; c < 32; c++) {
            float e = __expf(row[c] - m);
            s += e;
            row[c] = f2tf(e);
        }
        s += __shfl_xor_sync(0xffffffffu, s, 1);
        if (!half) sRcp[r] = 1.f / s;
    }
    __syncwarp();

    // O = P V  (16x32 per warp), scale by 1/rowsum in epilogue
    float oacc[4][4];
#pragma unroll
    for (int n = 0; n < 4; n++)
#pragma unroll
        for (int j = 0; j < 4; j++) oacc[n][j] = 0.f;

#pragma unroll
    for (int ks = 0; ks < 8; ks++) {
        float a[4];
        int rr = r0 + g, c0 = ks * 8 + t4;
        a[0] = sP[rr * 68 + c0];     a[1] = sP[(rr + 8) * 68 + c0];
        a[2] = sP[rr * 68 + c0 + 4]; a[3] = sP[(rr + 8) * 68 + c0 + 4];
#pragma unroll
        for (int ni = 0; ni < 4; ni++) {
            float b[2];
            b[0] = sV[c0 * 36 + ni * 8 + g];
            b[1] = sV[(c0 + 4) * 36 + ni * 8 + g];
            mma_tf32(oacc[ni], a, b);
        }
    }

#pragma unroll
    for (int ni = 0; ni < 4; ni++)
#pragma unroll
        for (int j = 0; j < 4; j++) {
            int r = r0 + g + ((j >> 1) << 3);
            int d = ni * 8 + 2 * t4 + (j & 1);
            g_ao[((size_t)widx * 64 + r) * 512 + head * 32 + d] = oacc[ni][j] * sRcp[r];
        }
}

// ---------------- launch ----------------
extern "C" void kernel_launch(void* const* d_in, const int* in_sizes, int n_in,
                              void* d_out, int out_size) {
    const float* x      = (const float*)d_in[0];
    const float* qkv_w  = (const float*)d_in[1];
    const float* qkv_b  = (const float*)d_in[2];
    const float* proj_w = (const float*)d_in[3];
    const float* proj_b = (const float*)d_in[4];
    const float* tbl    = (const float*)d_in[5];
    float* out = (float*)d_out;

    const int smem = GEMM_SMEM_FLOATS * 4;  // 52224 B > 48K -> needs attribute
    cudaFuncSetAttribute(gemm3x<0>, cudaFuncAttributeMaxDynamicSharedMemorySize, smem);
    cudaFuncSetAttribute(gemm3x<1>, cudaFuncAttributeMaxDynamicSharedMemorySize, smem);

    gemm3x<0><<<NWIN, 256, smem>>>(x, qkv_w, qkv_b, nullptr);
    attn_kernel<<<NWIN * NHEADS, 128>>>(tbl);
    gemm3x<1><<<NWIN, 256, smem>>>(nullptr, proj_w, proj_b, out);
}

// round 3
// speedup vs baseline: 1.5403x; 1.5403x over previous
#include <cuda_runtime.h>
#include <cuda_bf16.h>

// ---------------- problem constants ----------------
#define NHEADS 16
#define CDIM   512
#define HD     32
#define NTOK   64            // tokens per window (8x8)
#define NWIN   2048          // 8 batches * 16 * 16 windows
#define NROWS  (NWIN * NTOK) // 131072 total tokens

// ---------------- scratch (device globals; allocation-free) ----------------
__device__ float g_q[(size_t)NWIN * NHEADS * NTOK * HD];   // 256 MiB
__device__ float g_k[(size_t)NWIN * NHEADS * NTOK * HD];   // 256 MiB
__device__ float g_v[(size_t)NWIN * NHEADS * NTOK * HD];   // 256 MiB

// pre-split bf16 operands (hi/lo)
__device__ __align__(256) __nv_bfloat16 g_xh[(size_t)NROWS * CDIM];   // 128 MiB
__device__ __align__(256) __nv_bfloat16 g_xl[(size_t)NROWS * CDIM];
__device__ __align__(256) __nv_bfloat16 g_aoh[(size_t)NROWS * CDIM];  // attention out hi
__device__ __align__(256) __nv_bfloat16 g_aol[(size_t)NROWS * CDIM];  // attention out lo
__device__ __align__(256) __nv_bfloat16 g_wth[1536 * 512];            // qkv_w^T hi  [n][k]
__device__ __align__(256) __nv_bfloat16 g_wtl[1536 * 512];
__device__ __align__(256) __nv_bfloat16 g_pth[512 * 512];             // proj_w^T hi [n][k]
__device__ __align__(256) __nv_bfloat16 g_ptl[512 * 512];

// ---------------- helpers ----------------
__device__ __forceinline__ float f2tf(float x) {
    unsigned u;
    asm("cvt.rna.tf32.f32 %0, %1;" : "=r"(u) : "f"(x));
    return __uint_as_float(u);
}

// m16n8k8 tf32 mma (attention kernel)
__device__ __forceinline__ void mma_tf32(float c[4], const float a[4], const float b[2]) {
    asm volatile(
        "mma.sync.aligned.m16n8k8.row.col.f32.tf32.tf32.f32 "
        "{%0,%1,%2,%3},{%4,%5,%6,%7},{%8,%9},{%0,%1,%2,%3};\n"
        : "+f"(c[0]), "+f"(c[1]), "+f"(c[2]), "+f"(c[3])
        : "r"(__float_as_uint(a[0])), "r"(__float_as_uint(a[1])),
          "r"(__float_as_uint(a[2])), "r"(__float_as_uint(a[3])),
          "r"(__float_as_uint(b[0])), "r"(__float_as_uint(b[1])));
}

// m16n8k16 bf16 mma (GEMMs)
__device__ __forceinline__ void mma_bf16(float c[4], const unsigned a[4], const unsigned b[2]) {
    asm volatile(
        "mma.sync.aligned.m16n8k16.row.col.f32.bf16.bf16.f32 "
        "{%0,%1,%2,%3},{%4,%5,%6,%7},{%8,%9},{%0,%1,%2,%3};\n"
        : "+f"(c[0]), "+f"(c[1]), "+f"(c[2]), "+f"(c[3])
        : "r"(a[0]), "r"(a[1]), "r"(a[2]), "r"(a[3]), "r"(b[0]), "r"(b[1]));
}

__device__ __forceinline__ void cpa16(void* dst, const void* src) {
    unsigned d = (unsigned)__cvta_generic_to_shared(dst);
    asm volatile("cp.async.cg.shared.global [%0], [%1], 16;\n" :: "r"(d), "l"(src));
}
__device__ __forceinline__ unsigned lds32(const __nv_bfloat16* p) {
    return *reinterpret_cast<const unsigned*>(p);
}

// token n of window widx -> row index in flat (B*H*W) space
__device__ __forceinline__ long xrow(int widx, int n) {
    int b  = widx >> 8;
    int hy = (widx >> 4) & 15;
    int wx = widx & 15;
    int h  = hy * 8 + (n >> 3);
    int w  = wx * 8 + (n & 7);
    return ((long)((b << 7) + h) << 7) + w;
}

// ---------------- prep: split x into hi/lo bf16 ----------------
__global__ __launch_bounds__(256) void split_x_kernel(const float* __restrict__ x) {
    size_t i = (size_t)blockIdx.x * 256 + threadIdx.x;   // one float4 per thread
    float4 v = reinterpret_cast<const float4*>(x)[i];
    __nv_bfloat16 h0 = __float2bfloat16(v.x);
    __nv_bfloat16 h1 = __float2bfloat16(v.y);
    __nv_bfloat16 h2 = __float2bfloat16(v.z);
    __nv_bfloat16 h3 = __float2bfloat16(v.w);
    __nv_bfloat16 l0 = __float2bfloat16(v.x - __bfloat162float(h0));
    __nv_bfloat16 l1 = __float2bfloat16(v.y - __bfloat162float(h1));
    __nv_bfloat16 l2 = __float2bfloat16(v.z - __bfloat162float(h2));
    __nv_bfloat16 l3 = __float2bfloat16(v.w - __bfloat162float(h3));
    reinterpret_cast<__nv_bfloat162*>(g_xh)[2 * i + 0] = __halves2bfloat162(h0, h1);
    reinterpret_cast<__nv_bfloat162*>(g_xh)[2 * i + 1] = __halves2bfloat162(h2, h3);
    reinterpret_cast<__nv_bfloat162*>(g_xl)[2 * i + 0] = __halves2bfloat162(l0, l1);
    reinterpret_cast<__nv_bfloat162*>(g_xl)[2 * i + 1] = __halves2bfloat162(l2, l3);
}

// ---------------- prep: split + transpose weights ([K][N] -> [N][K] hi/lo) ----------------
template <int WSEL>  // 0: qkv (N=1536), 1: proj (N=512)
__global__ __launch_bounds__(256) void split_w_kernel(const float* __restrict__ W) {
    constexpr int N = (WSEL == 0) ? 1536 : 512;
    int idx = blockIdx.x * 256 + threadIdx.x;   // idx = n*512 + k
    int n = idx >> 9, k = idx & 511;
    float v = W[(size_t)k * N + n];
    __nv_bfloat16 h = __float2bfloat16(v);
    __nv_bfloat16 l = __float2bfloat16(v - __bfloat162float(h));
    if (WSEL == 0) { g_wth[idx] = h; g_wtl[idx] = l; }
    else           { g_pth[idx] = h; g_ptl[idx] = l; }
}

// ---------------- 3xBF16 GEMM ----------------
// MODE 0: QKV (A = pre-split x gathered by window, B = qkv_w^T), scatter to g_q/g_k/g_v
// MODE 1: proj (A = pre-split attention out,       B = proj_w^T), scatter to out
// Block 256 threads (8 warps, 2x4), Mtile=64, Ntile=128, Ktile=32, k16 mma, 2-stage cp.async.
#define A_H   0
#define A_L   2560
#define B_H   5120
#define B_L   10240
#define STAGE 15360   // bf16 elements per stage
#define GEMM_SMEM_BYTES (2 * STAGE * 2)  // 61440

template <int MODE>
__global__ __launch_bounds__(256) void gemm_bf16_3x(
    const float* __restrict__ bias, float* __restrict__ out)
{
    constexpr int NT = (MODE == 0) ? 12 : 4;
    extern __shared__ __nv_bfloat16 sm[];

    const int widx = blockIdx.x;
    const int tid  = threadIdx.x;
    const int wid  = tid >> 5, lane = tid & 31;
    const int g    = lane >> 2, t4 = lane & 3;
    const int wm   = wid & 1,  wn  = wid >> 1;

    const __nv_bfloat16* APh = (MODE == 0) ? g_xh : g_aoh;
    const __nv_bfloat16* APl = (MODE == 0) ? g_xl : g_aol;
    const __nv_bfloat16* BPh = (MODE == 0) ? g_wth : g_pth;
    const __nv_bfloat16* BPl = (MODE == 0) ? g_wtl : g_ptl;

    // per-thread cp.async task descriptors
    const __nv_bfloat16* aBase[2]; unsigned aDst[2];
#pragma unroll
    for (int i = 0; i < 2; i++) {
        int idx = tid + i * 256;               // 512 A tasks (16B each)
        int r = idx >> 3, rem = idx & 7, arr = rem >> 2, c = rem & 3;
        size_t rowb = (MODE == 0) ? (size_t)xrow(widx, r) * 512
                                  : ((size_t)widx * 64 + r) * 512;
        aBase[i] = (arr ? APl : APh) + rowb + c * 8;
        aDst[i]  = (arr ? A_L : A_H) + r * 40 + c * 8;
    }
    const __nv_bfloat16* bBase[4]; unsigned bDst[4];
#pragma unroll
    for (int i = 0; i < 4; i++) {
        int idx = tid + i * 256;               // 1024 B tasks
        int n = idx >> 3, rem = idx & 7, arr = rem >> 2, c = rem & 3;
        bBase[i] = (arr ? BPl : BPh) + (size_t)n * 512 + c * 8;
        bDst[i]  = (arr ? B_L : B_H) + n * 40 + c * 8;
    }

    for (int nt = 0; nt < NT; ++nt) {
        float acc[2][4][4];
#pragma unroll
        for (int a = 0; a < 2; a++)
#pragma unroll
            for (int b = 0; b < 4; b++)
#pragma unroll
                for (int c = 0; c < 4; c++) acc[a][b][c] = 0.f;

        const size_t bNT = (size_t)nt * 128 * 512;

        // issue stage 0
        {
#pragma unroll
            for (int i = 0; i < 2; i++) cpa16(sm + aDst[i], aBase[i]);
#pragma unroll
            for (int i = 0; i < 4; i++) cpa16(sm + bDst[i], bBase[i] + bNT);
            asm volatile("cp.async.commit_group;\n");
        }

        for (int kt = 0; kt < 16; ++kt) {
            if (kt < 15) {
                unsigned sb = ((kt + 1) & 1) * STAGE;
                int ko = (kt + 1) * 32;
#pragma unroll
                for (int i = 0; i < 2; i++) cpa16(sm + sb + aDst[i], aBase[i] + ko);
#pragma unroll
                for (int i = 0; i < 4; i++) cpa16(sm + sb + bDst[i], bBase[i] + bNT + ko);
                asm volatile("cp.async.commit_group;\n");
                asm volatile("cp.async.wait_group 1;\n");
            } else {
                asm volatile("cp.async.wait_group 0;\n");
            }
            __syncthreads();

            const __nv_bfloat16* S = sm + (kt & 1) * STAGE;
#pragma unroll
            for (int ks2 = 0; ks2 < 2; ks2++) {
                const int k0 = ks2 * 16 + 2 * t4;
                unsigned ah[2][4], al[2][4];
#pragma unroll
                for (int mi = 0; mi < 2; mi++) {
                    int r0 = wm * 32 + mi * 16 + g;
                    const __nv_bfloat16* p = S + A_H + r0 * 40 + k0;
                    ah[mi][0] = lds32(p);            ah[mi][1] = lds32(p + 8 * 40);
                    ah[mi][2] = lds32(p + 8);        ah[mi][3] = lds32(p + 8 * 40 + 8);
                    const __nv_bfloat16* q = p + (A_L - A_H);
                    al[mi][0] = lds32(q);            al[mi][1] = lds32(q + 8 * 40);
                    al[mi][2] = lds32(q + 8);        al[mi][3] = lds32(q + 8 * 40 + 8);
                }
                unsigned bh[4][2], bl[4][2];
#pragma unroll
                for (int ni = 0; ni < 4; ni++) {
                    int n = wn * 32 + ni * 8 + g;
                    const __nv_bfloat16* p = S + B_H + n * 40 + k0;
                    bh[ni][0] = lds32(p); bh[ni][1] = lds32(p + 8);
                    const __nv_bfloat16* q = p + (B_L - B_H);
                    bl[ni][0] = lds32(q); bl[ni][1] = lds32(q + 8);
                }
#pragma unroll
                for (int mi = 0; mi < 2; mi++)
#pragma unroll
                    for (int ni = 0; ni < 4; ni++) {
                        mma_bf16(acc[mi][ni], al[mi], bh[ni]);  // lo*hi
                        mma_bf16(acc[mi][ni], ah[mi], bl[ni]);  // hi*lo
                        mma_bf16(acc[mi][ni], ah[mi], bh[ni]);  // hi*hi
                    }
            }
            __syncthreads();
        }

        // epilogue: bias + scatter
#pragma unroll
        for (int mi = 0; mi < 2; mi++)
#pragma unroll
            for (int ni = 0; ni < 4; ni++)
#pragma unroll
                for (int j = 0; j < 4; j++) {
                    int rl = wm * 32 + mi * 16 + g + ((j >> 1) << 3);
                    int cl = wn * 32 + ni * 8 + 2 * t4 + (j & 1);
                    int co = nt * 128 + cl;
                    float v = acc[mi][ni][j] + __ldg(bias + co);
                    if (MODE == 0) {
                        int part = co >> 9, cc = co & 511;
                        int hh = cc >> 5, d = cc & 31;
                        float* dst = (part == 0) ? g_q : ((part == 1) ? g_k : g_v);
                        dst[(((size_t)widx * 16 + hh) * 64 + rl) * 32 + d] = v;
                    } else {
                        out[xrow(widx, rl) * 512L + co] = v;
                    }
                }
    }
}

// ---------------- attention: one block per (window, head), 4 warps x 16 query rows ----
__global__ __launch_bounds__(128) void attn_kernel(const float* __restrict__ tbl) {
    __shared__ float sQ[64 * 36];
    __shared__ float sK[64 * 36];
    __shared__ float sV[64 * 36];
    __shared__ float sP[64 * 68];
    __shared__ float sRcp[64];

    const int bx   = blockIdx.x;
    const int widx = bx >> 4, head = bx & 15;
    const int tid  = threadIdx.x, wid = tid >> 5, lane = tid & 31;
    const int g    = lane >> 2, t4 = lane & 3;
    const size_t base = (size_t)bx * 2048;

#pragma unroll
    for (int i = 0; i < 4; i++) {
        int idx = tid + i * 128;
        int r = idx >> 3, c4 = idx & 7;
        int sb = r * 36 + c4 * 4;
        float4 q = *reinterpret_cast<const float4*>(g_q + base + (size_t)idx * 4);
        float4 k = *reinterpret_cast<const float4*>(g_k + base + (size_t)idx * 4);
        float4 v = *reinterpret_cast<const float4*>(g_v + base + (size_t)idx * 4);
        sQ[sb] = f2tf(q.x); sQ[sb + 1] = f2tf(q.y); sQ[sb + 2] = f2tf(q.z); sQ[sb + 3] = f2tf(q.w);
        sK[sb] = f2tf(k.x); sK[sb + 1] = f2tf(k.y); sK[sb + 2] = f2tf(k.z); sK[sb + 3] = f2tf(k.w);
        sV[sb] = f2tf(v.x); sV[sb + 1] = f2tf(v.y); sV[sb + 2] = f2tf(v.z); sV[sb + 3] = f2tf(v.w);
    }
    __syncthreads();

    const int r0 = wid * 16;

    float sacc[8][4];
#pragma unroll
    for (int n = 0; n < 8; n++)
#pragma unroll
        for (int j = 0; j < 4; j++) sacc[n][j] = 0.f;

#pragma unroll
    for (int ks = 0; ks < 4; ks++) {
        float a[4];
        int rr = r0 + g, c0 = ks * 8 + t4;
        a[0] = sQ[rr * 36 + c0];     a[1] = sQ[(rr + 8) * 36 + c0];
        a[2] = sQ[rr * 36 + c0 + 4]; a[3] = sQ[(rr + 8) * 36 + c0 + 4];
#pragma unroll
        for (int ni = 0; ni < 8; ni++) {
            float b[2];
            int n = ni * 8 + g;
            b[0] = sK[n * 36 + c0];
            b[1] = sK[n * 36 + c0 + 4];
            mma_tf32(sacc[ni], a, b);
        }
    }

    const float scale = 0.17677669529663687f;
#pragma unroll
    for (int ni = 0; ni < 8; ni++)
#pragma unroll
        for (int j = 0; j < 4; j++) {
            int r = r0 + g + ((j >> 1) << 3);
            int c = ni * 8 + 2 * t4 + (j & 1);
            int idx = ((r >> 3) - (c >> 3) + 7) * 15 + ((r & 7) - (c & 7) + 7);
            sP[r * 68 + c] = sacc[ni][j] * scale + __ldg(tbl + idx * 16 + head);
        }
    __syncwarp();

    {
        int r = r0 + (lane >> 1);
        int half = lane & 1;
        float* row = sP + r * 68 + half * 32;
        float m = row[0];
#pragma unroll
        for (int c = 1; c < 32; c++) m = fmaxf(m, row[c]);
        m = fmaxf(m, __shfl_xor_sync(0xffffffffu, m, 1));
        float s = 0.f;
#pragma unroll
        for (int c = 0; c < 32; c++) {
            float e = __expf(row[c] - m);
            s += e;
            row[c] = f2tf(e);
        }
        s += __shfl_xor_sync(0xffffffffu, s, 1);
        if (!half) sRcp[r] = 1.f / s;
    }
    __syncwarp();

    float oacc[4][4];
#pragma unroll
    for (int n = 0; n < 4; n++)
#pragma unroll
        for (int j = 0; j < 4; j++) oacc[n][j] = 0.f;

#pragma unroll
    for (int ks = 0; ks < 8; ks++) {
        float a[4];
        int rr = r0 + g, c0 = ks * 8 + t4;
        a[0] = sP[rr * 68 + c0];     a[1] = sP[(rr + 8) * 68 + c0];
        a[2] = sP[rr * 68 + c0 + 4]; a[3] = sP[(rr + 8) * 68 + c0 + 4];
#pragma unroll
        for (int ni = 0; ni < 4; ni++) {
            float b[2];
            b[0] = sV[c0 * 36 + ni * 8 + g];
            b[1] = sV[(c0 + 4) * 36 + ni * 8 + g];
            mma_tf32(oacc[ni], a, b);
        }
    }

    // epilogue: normalize and write PRE-SPLIT bf16 hi/lo for the proj GEMM
#pragma unroll
    for (int ni = 0; ni < 4; ni++)
#pragma unroll
        for (int j = 0; j < 4; j++) {
            int r = r0 + g + ((j >> 1) << 3);
            int d = ni * 8 + 2 * t4 + (j & 1);
            size_t off = ((size_t)widx * 64 + r) * 512 + head * 32 + d;
            float v = oacc[ni][j] * sRcp[r];
            __nv_bfloat16 h = __float2bfloat16(v);
            g_aoh[off] = h;
            g_aol[off] = __float2bfloat16(v - __bfloat162float(h));
        }
}

// ---------------- launch ----------------
extern "C" void kernel_launch(void* const* d_in, const int* in_sizes, int n_in,
                              void* d_out, int out_size) {
    const float* x      = (const float*)d_in[0];
    const float* qkv_w  = (const float*)d_in[1];
    const float* qkv_b  = (const float*)d_in[2];
    const float* proj_w = (const float*)d_in[3];
    const float* proj_b = (const float*)d_in[4];
    const float* tbl    = (const float*)d_in[5];
    float* out = (float*)d_out;

    cudaFuncSetAttribute(gemm_bf16_3x<0>, cudaFuncAttributeMaxDynamicSharedMemorySize, GEMM_SMEM_BYTES);
    cudaFuncSetAttribute(gemm_bf16_3x<1>, cudaFuncAttributeMaxDynamicSharedMemorySize, GEMM_SMEM_BYTES);

    split_x_kernel<<<(NROWS * (CDIM / 4)) / 256, 256>>>(x);        // 65536 blocks
    split_w_kernel<0><<<(1536 * 512) / 256, 256>>>(qkv_w);
    split_w_kernel<1><<<(512 * 512) / 256, 256>>>(proj_w);

    gemm_bf16_3x<0><<<NWIN, 256, GEMM_SMEM_BYTES>>>(qkv_b, nullptr);
    attn_kernel<<<NWIN * NHEADS, 128>>>(tbl);
    gemm_bf16_3x<1><<<NWIN, 256, GEMM_SMEM_BYTES>>>(proj_b, out);
}

// round 8
// speedup vs baseline: 1.8264x; 1.1858x over previous
#include <cuda_runtime.h>
#include <cuda_bf16.h>
#include <cstdint>

// ---------------- problem constants ----------------
#define NHEADS 16
#define CDIM   512
#define HD     32
#define NTOK   64
#define NWIN   2048
#define NROWS  (NWIN * NTOK)

// ---------------- scratch ----------------
__device__ float g_q[(size_t)NWIN * NHEADS * NTOK * HD];
__device__ float g_k[(size_t)NWIN * NHEADS * NTOK * HD];
__device__ float g_v[(size_t)NWIN * NHEADS * NTOK * HD];

__device__ __align__(256) __nv_bfloat16 g_xh[(size_t)NROWS * CDIM];
__device__ __align__(256) __nv_bfloat16 g_xl[(size_t)NROWS * CDIM];
__device__ __align__(256) __nv_bfloat16 g_aoh[(size_t)NROWS * CDIM];
__device__ __align__(256) __nv_bfloat16 g_aol[(size_t)NROWS * CDIM];
__device__ __align__(256) __nv_bfloat16 g_wth[1536 * 512];   // qkv_w^T hi  [n][k]
__device__ __align__(256) __nv_bfloat16 g_wtl[1536 * 512];
__device__ __align__(256) __nv_bfloat16 g_pth[512 * 512];    // proj_w^T hi [n][k]
__device__ __align__(256) __nv_bfloat16 g_ptl[512 * 512];

// ---------------- helpers ----------------
__device__ __forceinline__ float f2tf(float x) {
    unsigned u; asm("cvt.rna.tf32.f32 %0, %1;" : "=r"(u) : "f"(x));
    return __uint_as_float(u);
}
__device__ __forceinline__ void mma_tf32(float c[4], const float a[4], const float b[2]) {
    asm volatile(
        "mma.sync.aligned.m16n8k8.row.col.f32.tf32.tf32.f32 "
        "{%0,%1,%2,%3},{%4,%5,%6,%7},{%8,%9},{%0,%1,%2,%3};\n"
        : "+f"(c[0]), "+f"(c[1]), "+f"(c[2]), "+f"(c[3])
        : "r"(__float_as_uint(a[0])), "r"(__float_as_uint(a[1])),
          "r"(__float_as_uint(a[2])), "r"(__float_as_uint(a[3])),
          "r"(__float_as_uint(b[0])), "r"(__float_as_uint(b[1])));
}
__device__ __forceinline__ void mma_bf16(float c[4], const unsigned a[4], const unsigned b[2]) {
    asm volatile(
        "mma.sync.aligned.m16n8k16.row.col.f32.bf16.bf16.f32 "
        "{%0,%1,%2,%3},{%4,%5,%6,%7},{%8,%9},{%0,%1,%2,%3};\n"
        : "+f"(c[0]), "+f"(c[1]), "+f"(c[2]), "+f"(c[3])
        : "r"(a[0]), "r"(a[1]), "r"(a[2]), "r"(a[3]), "r"(b[0]), "r"(b[1]));
}
__device__ __forceinline__ void lm4(unsigned r[4], uint32_t addr) {
    asm volatile("ldmatrix.sync.aligned.m8n8.x4.shared.b16 {%0,%1,%2,%3}, [%4];"
                 : "=r"(r[0]), "=r"(r[1]), "=r"(r[2]), "=r"(r[3]) : "r"(addr));
}
__device__ __forceinline__ void cpa16(uint32_t dst, const void* src) {
    asm volatile("cp.async.cg.shared.global [%0], [%1], 16;\n" :: "r"(dst), "l"(src));
}
__device__ __forceinline__ long xrow(int widx, int n) {
    int b  = widx >> 8;
    int hy = (widx >> 4) & 15;
    int wx = widx & 15;
    int h  = hy * 8 + (n >> 3);
    int w  = wx * 8 + (n & 7);
    return ((long)((b << 7) + h) << 7) + w;
}

// ---------------- prep kernels ----------------
__global__ __launch_bounds__(256) void split_x_kernel(const float* __restrict__ x) {
    size_t i = (size_t)blockIdx.x * 256 + threadIdx.x;
    float4 v = reinterpret_cast<const float4*>(x)[i];
    __nv_bfloat16 h0 = __float2bfloat16(v.x), h1 = __float2bfloat16(v.y);
    __nv_bfloat16 h2 = __float2bfloat16(v.z), h3 = __float2bfloat16(v.w);
    __nv_bfloat16 l0 = __float2bfloat16(v.x - __bfloat162float(h0));
    __nv_bfloat16 l1 = __float2bfloat16(v.y - __bfloat162float(h1));
    __nv_bfloat16 l2 = __float2bfloat16(v.z - __bfloat162float(h2));
    __nv_bfloat16 l3 = __float2bfloat16(v.w - __bfloat162float(h3));
    reinterpret_cast<__nv_bfloat162*>(g_xh)[2 * i + 0] = __halves2bfloat162(h0, h1);
    reinterpret_cast<__nv_bfloat162*>(g_xh)[2 * i + 1] = __halves2bfloat162(h2, h3);
    reinterpret_cast<__nv_bfloat162*>(g_xl)[2 * i + 0] = __halves2bfloat162(l0, l1);
    reinterpret_cast<__nv_bfloat162*>(g_xl)[2 * i + 1] = __halves2bfloat162(l2, l3);
}
template <int WSEL>
__global__ __launch_bounds__(256) void split_w_kernel(const float* __restrict__ W) {
    constexpr int N = (WSEL == 0) ? 1536 : 512;
    int idx = blockIdx.x * 256 + threadIdx.x;
    int n = idx >> 9, k = idx & 511;
    float v = W[(size_t)k * N + n];
    __nv_bfloat16 h = __float2bfloat16(v);
    __nv_bfloat16 l = __float2bfloat16(v - __bfloat162float(h));
    if (WSEL == 0) { g_wth[idx] = h; g_wtl[idx] = l; }
    else           { g_pth[idx] = h; g_ptl[idx] = l; }
}

// ---------------- ldmatrix bf16 3-split GEMM ----------------
// CTA tile M=128 x N=128, Ktile=32, 512 threads (4x4 warps, warp tile 32x32).
// 3-stage cp.async pipeline. SMEM per stage (32KB):
//   A_hi [0,8K) A_lo [8K,16K) B_hi [16K,24K) B_lo [24K,32K)
// Rows are 64B (32 bf16, K-major); 16B chunk index swizzled: c' = c ^ ((row>>1)&3)
// -> conflict-free ldmatrix 8-row phases (bank-group = 4*(row&1) + c').
#define STAGE_B  32768
#define GEMM_SMEM (3 * STAGE_B)

template <int MODE>   // 0: QKV (NT=12), 1: proj (NT=4)
__global__ __launch_bounds__(512, 1) void gemm_lm(
    const float* __restrict__ bias, float* __restrict__ out)
{
    constexpr int NT = (MODE == 0) ? 12 : 4;
    extern __shared__ __align__(128) char dyn[];
    const uint32_t smem0 = (uint32_t)__cvta_generic_to_shared(dyn);

    const int bx   = blockIdx.x;
    const int tid  = threadIdx.x;
    const int wid  = tid >> 5, lane = tid & 31;
    const int g    = lane >> 2, t4 = lane & 3;
    const int wm   = wid & 3, wn = wid >> 2;

    const __nv_bfloat16* APh = (MODE == 0) ? g_xh : g_aoh;
    const __nv_bfloat16* APl = (MODE == 0) ? g_xl : g_aol;
    const __nv_bfloat16* BPh = (MODE == 0) ? g_wth : g_pth;
    const __nv_bfloat16* BPl = (MODE == 0) ? g_wtl : g_ptl;

    // ---- cp.async task descriptors: 1024 A tasks + 1024 B tasks, 16B each ----
    const __nv_bfloat16* aPtr[2]; uint32_t aDst[2];
#pragma unroll
    for (int i = 0; i < 2; i++) {
        int idx = tid + i * 512;
        int row = idx >> 3, rem = idx & 7;
        int ch = rem & 3, half = rem >> 2;
        long rowb = (MODE == 0) ? xrow(2 * bx + (row >> 6), row & 63) * 512L
                                : ((long)bx * 128 + row) * 512L;
        aPtr[i] = (half ? APl : APh) + rowb + ch * 8;
        aDst[i] = half * 8192u + row * 64u + (((uint32_t)(ch ^ ((row >> 1) & 3))) << 4);
    }
    const __nv_bfloat16* bPtr[2]; uint32_t bDst[2];
#pragma unroll
    for (int i = 0; i < 2; i++) {
        int idx = tid + i * 512;
        int row = idx >> 3, rem = idx & 7;
        int ch = rem & 3, half = rem >> 2;
        bPtr[i] = (half ? BPl : BPh) + (size_t)row * 512 + ch * 8;
        bDst[i] = 16384u + half * 8192u + row * 64u +
                  (((uint32_t)(ch ^ ((row >> 1) & 3))) << 4);
    }

    // ---- ldmatrix per-lane base offsets ----
    const int rowA = wm * 32 + (lane & 15);
    const int cbA  = (lane >> 4) & 1;
    const uint32_t aLane = rowA * 64u + (((uint32_t)(cbA ^ ((rowA >> 1) & 3))) << 4);
    const int rowB = wn * 32 + (lane & 7) + (((lane >> 4) & 1) << 3);
    const int cbB  = (lane >> 3) & 1;
    const uint32_t bLane = 16384u + rowB * 64u +
                           (((uint32_t)(cbB ^ ((rowB >> 1) & 3))) << 4);

    const float2* bias2 = reinterpret_cast<const float2*>(bias);

    for (int nt = 0; nt < NT; ++nt) {
        const uint32_t ntOff = (uint32_t)nt * 65536u;   // nt*128 rows * 512 k

        float acc[2][4][4];
#pragma unroll
        for (int a = 0; a < 2; a++)
#pragma unroll
            for (int b = 0; b < 4; b++)
#pragma unroll
                for (int c = 0; c < 4; c++) acc[a][b][c] = 0.f;

        // prologue: chunks 0,1 into stages 0,1
#pragma unroll
        for (int s = 0; s < 2; s++) {
            uint32_t sb = smem0 + s * STAGE_B;
#pragma unroll
            for (int i = 0; i < 2; i++) cpa16(sb + aDst[i], aPtr[i] + s * 32);
#pragma unroll
            for (int i = 0; i < 2; i++) cpa16(sb + bDst[i], bPtr[i] + ntOff + s * 32);
            asm volatile("cp.async.commit_group;\n");
        }

        int sIss = 2;      // stage for next issue
        int sCmp = 0;      // stage being computed
        for (int c = 0; c < 16; ++c) {
            if (c + 2 < 16) {
                uint32_t sb = smem0 + sIss * STAGE_B;
                int kc = (c + 2) * 32;
#pragma unroll
                for (int i = 0; i < 2; i++) cpa16(sb + aDst[i], aPtr[i] + kc);
#pragma unroll
                for (int i = 0; i < 2; i++) cpa16(sb + bDst[i], bPtr[i] + ntOff + kc);
                asm volatile("cp.async.commit_group;\n");
                asm volatile("cp.async.wait_group 2;\n");
                if (++sIss == 3) sIss = 0;
            } else {
                asm volatile("cp.async.wait_group 0;\n");
            }
            __syncthreads();

            const uint32_t sb = smem0 + sCmp * STAGE_B;
            const uint32_t aB0 = sb + aLane;
            const uint32_t bB0 = sb + bLane;
#pragma unroll
            for (int s16 = 0; s16 < 2; s16++) {
                const uint32_t aA = aB0 ^ (s16 << 5);
                const uint32_t bA = bB0 ^ (s16 << 5);
                unsigned Ah[2][4], Al[2][4];
                lm4(Ah[0], aA);          lm4(Ah[1], aA + 1024);
                lm4(Al[0], aA + 8192);   lm4(Al[1], aA + 8192 + 1024);
#pragma unroll
                for (int nn = 0; nn < 2; nn++) {
                    unsigned Bh[4], Bl[4];
                    lm4(Bh, bA + nn * 1024);
                    lm4(Bl, bA + nn * 1024 + 8192);
#pragma unroll
                    for (int mi = 0; mi < 2; mi++) {
                        mma_bf16(acc[mi][2 * nn + 0], Al[mi], Bh + 0);
                        mma_bf16(acc[mi][2 * nn + 0], Ah[mi], Bl + 0);
                        mma_bf16(acc[mi][2 * nn + 0], Ah[mi], Bh + 0);
                        mma_bf16(acc[mi][2 * nn + 1], Al[mi], Bh + 2);
                        mma_bf16(acc[mi][2 * nn + 1], Ah[mi], Bl + 2);
                        mma_bf16(acc[mi][2 * nn + 1], Ah[mi], Bh + 2);
                    }
                }
            }
            __syncthreads();   // compute done before this stage is refilled
            if (++sCmp == 3) sCmp = 0;
        }

        // ---- epilogue: bias + scatter (float2 stores) ----
#pragma unroll
        for (int mi = 0; mi < 2; mi++)
#pragma unroll
            for (int ni = 0; ni < 4; ni++) {
                int col = wn * 32 + ni * 8 + 2 * t4;
                int co  = nt * 128 + col;
                float2 bb = __ldg(bias2 + (co >> 1));
#pragma unroll
                for (int jr = 0; jr < 2; jr++) {
                    int row = wm * 32 + mi * 16 + g + 8 * jr;
                    float2 v;
                    v.x = acc[mi][ni][2 * jr + 0] + bb.x;
                    v.y = acc[mi][ni][2 * jr + 1] + bb.y;
                    int widx = 2 * bx + (row >> 6), rl = row & 63;
                    if (MODE == 0) {
                        int part = co >> 9, head = (co >> 5) & 15, d = co & 31;
                        float* dst = (part == 0) ? g_q : ((part == 1) ? g_k : g_v);
                        *reinterpret_cast<float2*>(
                            dst + (((size_t)(widx * 16 + head) * 64 + rl) << 5) + d) = v;
                    } else {
                        *reinterpret_cast<float2*>(out + xrow(widx, rl) * 512L + co) = v;
                    }
                }
            }
    }
}

// ---------------- attention (unchanged, known-good) ----------------
__global__ __launch_bounds__(128) void attn_kernel(const float* __restrict__ tbl) {
    __shared__ float sQ[64 * 36];
    __shared__ float sK[64 * 36];
    __shared__ float sV[64 * 36];
    __shared__ float sP[64 * 68];
    __shared__ float sRcp[64];

    const int bx   = blockIdx.x;
    const int widx = bx >> 4, head = bx & 15;
    const int tid  = threadIdx.x, wid = tid >> 5, lane = tid & 31;
    const int g    = lane >> 2, t4 = lane & 3;
    const size_t base = (size_t)bx * 2048;

#pragma unroll
    for (int i = 0; i < 4; i++) {
        int idx = tid + i * 128;
        int r = idx >> 3, c4 = idx & 7;
        int sb = r * 36 + c4 * 4;
        float4 q = *reinterpret_cast<const float4*>(g_q + base + (size_t)idx * 4);
        float4 k = *reinterpret_cast<const float4*>(g_k + base + (size_t)idx * 4);
        float4 v = *reinterpret_cast<const float4*>(g_v + base + (size_t)idx * 4);
        sQ[sb] = f2tf(q.x); sQ[sb + 1] = f2tf(q.y); sQ[sb + 2] = f2tf(q.z); sQ[sb + 3] = f2tf(q.w);
        sK[sb] = f2tf(k.x); sK[sb + 1] = f2tf(k.y); sK[sb + 2] = f2tf(k.z); sK[sb + 3] = f2tf(k.w);
        sV[sb] = f2tf(v.x); sV[sb + 1] = f2tf(v.y); sV[sb + 2] = f2tf(v.z); sV[sb + 3] = f2tf(v.w);
    }
    __syncthreads();

    const int r0 = wid * 16;

    float sacc[8][4];
#pragma unroll
    for (int n = 0; n < 8; n++)
#pragma unroll
        for (int j = 0; j < 4; j++) sacc[n][j] = 0.f;

#pragma unroll
    for (int ks = 0; ks < 4; ks++) {
        float a[4];
        int rr = r0 + g, c0 = ks * 8 + t4;
        a[0] = sQ[rr * 36 + c0];     a[1] = sQ[(rr + 8) * 36 + c0];
        a[2] = sQ[rr * 36 + c0 + 4]; a[3] = sQ[(rr + 8) * 36 + c0 + 4];
#pragma unroll
        for (int ni = 0; ni < 8; ni++) {
            float b[2];
            int n = ni * 8 + g;
            b[0] = sK[n * 36 + c0];
            b[1] = sK[n * 36 + c0 + 4];
            mma_tf32(sacc[ni], a, b);
        }
    }

    const float scale = 0.17677669529663687f;
#pragma unroll
    for (int ni = 0; ni < 8; ni++)
#pragma unroll
        for (int j = 0; j < 4; j++) {
            int r = r0 + g + ((j >> 1) << 3);
            int c = ni * 8 + 2 * t4 + (j & 1);
            int idx = ((r >> 3) - (c >> 3) + 7) * 15 + ((r & 7) - (c & 7) + 7);
            sP[r * 68 + c] = sacc[ni][j] * scale + __ldg(tbl + idx * 16 + head);
        }
    __syncwarp();

    {
        int r = r0 + (lane >> 1);
        int half = lane & 1;
        float* row = sP + r * 68 + half * 32;
        float m = row[0];
#pragma unroll
        for (int c = 1; c < 32; c++) m = fmaxf(m, row[c]);
        m = fmaxf(m, __shfl_xor_sync(0xffffffffu, m, 1));
        float s = 0.f;
#pragma unroll
        for (int c = 0; c < 32; c++) {
            float e = __expf(row[c] - m);
            s += e;
            row[c] = f2tf(e);
        }
        s += __shfl_xor_sync(0xffffffffu, s, 1);
        if (!half) sRcp[r] = 1.f / s;
    }
    __syncwarp();

    float oacc[4][4];
#pragma unroll
    for (int n = 0; n < 4; n++)
#pragma unroll
        for (int j = 0; j < 4; j++) oacc[n][j] = 0.f;

#pragma unroll
    for (int ks = 0; ks < 8; ks++) {
        float a[4];
        int rr = r0 + g, c0 = ks * 8 + t4;
        a[0] = sP[rr * 68 + c0];     a[1] = sP[(rr + 8) * 68 + c0];
        a[2] = sP[rr * 68 + c0 + 4]; a[3] = sP[(rr + 8) * 68 + c0 + 4];
#pragma unroll
        for (int ni = 0; ni < 4; ni++) {
            float b[2];
            b[0] = sV[c0 * 36 + ni * 8 + g];
            b[1] = sV[(c0 + 4) * 36 + ni * 8 + g];
            mma_tf32(oacc[ni], a, b);
        }
    }

#pragma unroll
    for (int ni = 0; ni < 4; ni++)
#pragma unroll
        for (int j = 0; j < 4; j++) {
            int r = r0 + g + ((j >> 1) << 3);
            int d = ni * 8 + 2 * t4 + (j & 1);
            size_t off = ((size_t)widx * 64 + r) * 512 + head * 32 + d;
            float v = oacc[ni][j] * sRcp[r];
            __nv_bfloat16 h = __float2bfloat16(v);
            g_aoh[off] = h;
            g_aol[off] = __float2bfloat16(v - __bfloat162float(h));
        }
}

// ---------------- launch ----------------
extern "C" void kernel_launch(void* const* d_in, const int* in_sizes, int n_in,
                              void* d_out, int out_size) {
    const float* x      = (const float*)d_in[0];
    const float* qkv_w  = (const float*)d_in[1];
    const float* qkv_b  = (const float*)d_in[2];
    const float* proj_w = (const float*)d_in[3];
    const float* proj_b = (const float*)d_in[4];
    const float* tbl    = (const float*)d_in[5];
    float* out = (float*)d_out;

    cudaFuncSetAttribute(gemm_lm<0>, cudaFuncAttributeMaxDynamicSharedMemorySize, GEMM_SMEM);
    cudaFuncSetAttribute(gemm_lm<1>, cudaFuncAttributeMaxDynamicSharedMemorySize, GEMM_SMEM);

    split_x_kernel<<<(NROWS * (CDIM / 4)) / 256, 256>>>(x);
    split_w_kernel<0><<<(1536 * 512) / 256, 256>>>(qkv_w);
    split_w_kernel<1><<<(512 * 512) / 256, 256>>>(proj_w);

    gemm_lm<0><<<NROWS / 128, 512, GEMM_SMEM>>>(qkv_b, nullptr);
    attn_kernel<<<NWIN * NHEADS, 128>>>(tbl);
    gemm_lm<1><<<NROWS / 128, 512, GEMM_SMEM>>>(proj_b, out);
}

// round 9
// speedup vs baseline: 1.8891x; 1.0343x over previous
#include <cuda_runtime.h>
#include <cuda_bf16.h>
#include <cstdint>

// ---------------- problem constants ----------------
#define NHEADS 16
#define CDIM   512
#define HD     32
#define NTOK   64
#define NWIN   2048
#define NROWS  (NWIN * NTOK)

// ---------------- scratch ----------------
__device__ float g_q[(size_t)NWIN * NHEADS * NTOK * HD];
__device__ float g_k[(size_t)NWIN * NHEADS * NTOK * HD];
__device__ float g_v[(size_t)NWIN * NHEADS * NTOK * HD];

__device__ __align__(256) __nv_bfloat16 g_xh[(size_t)NROWS * CDIM];
__device__ __align__(256) __nv_bfloat16 g_xl[(size_t)NROWS * CDIM];
__device__ __align__(256) __nv_bfloat16 g_aoh[(size_t)NROWS * CDIM];
__device__ __align__(256) __nv_bfloat16 g_aol[(size_t)NROWS * CDIM];
__device__ __align__(256) __nv_bfloat16 g_wth[1536 * 512];   // qkv_w^T hi  [n][k]
__device__ __align__(256) __nv_bfloat16 g_wtl[1536 * 512];
__device__ __align__(256) __nv_bfloat16 g_pth[512 * 512];    // proj_w^T hi [n][k]
__device__ __align__(256) __nv_bfloat16 g_ptl[512 * 512];

// ---------------- helpers ----------------
__device__ __forceinline__ float f2tf(float x) {
    unsigned u; asm("cvt.rna.tf32.f32 %0, %1;" : "=r"(u) : "f"(x));
    return __uint_as_float(u);
}
__device__ __forceinline__ void mma_tf32(float c[4], const float a[4], const float b[2]) {
    asm volatile(
        "mma.sync.aligned.m16n8k8.row.col.f32.tf32.tf32.f32 "
        "{%0,%1,%2,%3},{%4,%5,%6,%7},{%8,%9},{%0,%1,%2,%3};\n"
        : "+f"(c[0]), "+f"(c[1]), "+f"(c[2]), "+f"(c[3])
        : "r"(__float_as_uint(a[0])), "r"(__float_as_uint(a[1])),
          "r"(__float_as_uint(a[2])), "r"(__float_as_uint(a[3])),
          "r"(__float_as_uint(b[0])), "r"(__float_as_uint(b[1])));
}
__device__ __forceinline__ void mma_bf16(float c[4], const unsigned a[4], const unsigned b[2]) {
    asm volatile(
        "mma.sync.aligned.m16n8k16.row.col.f32.bf16.bf16.f32 "
        "{%0,%1,%2,%3},{%4,%5,%6,%7},{%8,%9},{%0,%1,%2,%3};\n"
        : "+f"(c[0]), "+f"(c[1]), "+f"(c[2]), "+f"(c[3])
        : "r"(a[0]), "r"(a[1]), "r"(a[2]), "r"(a[3]), "r"(b[0]), "r"(b[1]));
}
__device__ __forceinline__ void lm4(unsigned r[4], uint32_t addr) {
    asm volatile("ldmatrix.sync.aligned.m8n8.x4.shared.b16 {%0,%1,%2,%3}, [%4];"
                 : "=r"(r[0]), "=r"(r[1]), "=r"(r[2]), "=r"(r[3]) : "r"(addr));
}
__device__ __forceinline__ void cpa16(uint32_t dst, const void* src) {
    asm volatile("cp.async.cg.shared.global [%0], [%1], 16;\n" :: "r"(dst), "l"(src));
}
__device__ __forceinline__ long xrow(int widx, int n) {
    int b  = widx >> 8;
    int hy = (widx >> 4) & 15;
    int wx = widx & 15;
    int h  = hy * 8 + (n >> 3);
    int w  = wx * 8 + (n & 7);
    return ((long)((b << 7) + h) << 7) + w;
}

// ---------------- prep kernels ----------------
__global__ __launch_bounds__(256) void split_x_kernel(const float* __restrict__ x) {
    size_t i = (size_t)blockIdx.x * 256 + threadIdx.x;
    float4 v = reinterpret_cast<const float4*>(x)[i];
    __nv_bfloat16 h0 = __float2bfloat16(v.x), h1 = __float2bfloat16(v.y);
    __nv_bfloat16 h2 = __float2bfloat16(v.z), h3 = __float2bfloat16(v.w);
    __nv_bfloat16 l0 = __float2bfloat16(v.x - __bfloat162float(h0));
    __nv_bfloat16 l1 = __float2bfloat16(v.y - __bfloat162float(h1));
    __nv_bfloat16 l2 = __float2bfloat16(v.z - __bfloat162float(h2));
    __nv_bfloat16 l3 = __float2bfloat16(v.w - __bfloat162float(h3));
    reinterpret_cast<__nv_bfloat162*>(g_xh)[2 * i + 0] = __halves2bfloat162(h0, h1);
    reinterpret_cast<__nv_bfloat162*>(g_xh)[2 * i + 1] = __halves2bfloat162(h2, h3);
    reinterpret_cast<__nv_bfloat162*>(g_xl)[2 * i + 0] = __halves2bfloat162(l0, l1);
    reinterpret_cast<__nv_bfloat162*>(g_xl)[2 * i + 1] = __halves2bfloat162(l2, l3);
}
template <int WSEL>
__global__ __launch_bounds__(256) void split_w_kernel(const float* __restrict__ W) {
    constexpr int N = (WSEL == 0) ? 1536 : 512;
    int idx = blockIdx.x * 256 + threadIdx.x;
    int n = idx >> 9, k = idx & 511;
    float v = W[(size_t)k * N + n];
    __nv_bfloat16 h = __float2bfloat16(v);
    __nv_bfloat16 l = __float2bfloat16(v - __bfloat162float(h));
    if (WSEL == 0) { g_wth[idx] = h; g_wtl[idx] = l; }
    else           { g_pth[idx] = h; g_ptl[idx] = l; }
}

// ---------------- ldmatrix bf16 3-split GEMM ----------------
// CTA tile M=128 x N=128, Ktile=32, 512 threads (4x4 warps, warp tile 32x32).
// FLAT 4-stage cp.async pipeline over all (nt, kt) chunks: prefetch distance 3,
// ONE __syncthreads per chunk (wait_group -> barrier -> refill -> compute).
// Epilogue is register-only, so next-nt prefetch continues across nt boundaries.
// SMEM per stage (32KB): A_hi [0,8K) A_lo [8K,16K) B_hi [16K,24K) B_lo [24K,32K)
// Rows are 64B (32 bf16, K-major); 16B chunk index swizzled: c' = c ^ ((row>>1)&3).
#define STAGE_B  32768
#define GEMM_SMEM (4 * STAGE_B)

template <int MODE>   // 0: QKV (NT=12), 1: proj (NT=4)
__global__ __launch_bounds__(512, 1) void gemm_lm(
    const float* __restrict__ bias, float* __restrict__ out)
{
    constexpr int NT = (MODE == 0) ? 12 : 4;
    constexpr int L  = NT * 16;              // total K-chunks across all nt
    extern __shared__ __align__(128) char dyn[];
    const uint32_t smem0 = (uint32_t)__cvta_generic_to_shared(dyn);

    const int bx   = blockIdx.x;
    const int tid  = threadIdx.x;
    const int wid  = tid >> 5, lane = tid & 31;
    const int g    = lane >> 2, t4 = lane & 3;
    const int wm   = wid & 3, wn = wid >> 2;

    const __nv_bfloat16* APh = (MODE == 0) ? g_xh : g_aoh;
    const __nv_bfloat16* APl = (MODE == 0) ? g_xl : g_aol;
    const __nv_bfloat16* BPh = (MODE == 0) ? g_wth : g_pth;
    const __nv_bfloat16* BPl = (MODE == 0) ? g_wtl : g_ptl;

    // ---- cp.async task descriptors: 1024 A tasks + 1024 B tasks, 16B each ----
    const __nv_bfloat16* aPtr[2]; uint32_t aDst[2];
#pragma unroll
    for (int i = 0; i < 2; i++) {
        int idx = tid + i * 512;
        int row = idx >> 3, rem = idx & 7;
        int ch = rem & 3, half = rem >> 2;
        long rowb = (MODE == 0) ? xrow(2 * bx + (row >> 6), row & 63) * 512L
                                : ((long)bx * 128 + row) * 512L;
        aPtr[i] = (half ? APl : APh) + rowb + ch * 8;
        aDst[i] = half * 8192u + row * 64u + (((uint32_t)(ch ^ ((row >> 1) & 3))) << 4);
    }
    const __nv_bfloat16* bPtr[2]; uint32_t bDst[2];
#pragma unroll
    for (int i = 0; i < 2; i++) {
        int idx = tid + i * 512;
        int row = idx >> 3, rem = idx & 7;
        int ch = rem & 3, half = rem >> 2;
        bPtr[i] = (half ? BPl : BPh) + (size_t)row * 512 + ch * 8;
        bDst[i] = 16384u + half * 8192u + row * 64u +
                  (((uint32_t)(ch ^ ((row >> 1) & 3))) << 4);
    }

    // ---- ldmatrix per-lane base offsets ----
    const int rowA = wm * 32 + (lane & 15);
    const int cbA  = (lane >> 4) & 1;
    const uint32_t aLane = rowA * 64u + (((uint32_t)(cbA ^ ((rowA >> 1) & 3))) << 4);
    const int rowB = wn * 32 + (lane & 7) + (((lane >> 4) & 1) << 3);
    const int cbB  = (lane >> 3) & 1;
    const uint32_t bLane = 16384u + rowB * 64u +
                           (((uint32_t)(cbB ^ ((rowB >> 1) & 3))) << 4);

    const float2* bias2 = reinterpret_cast<const float2*>(bias);

    float acc[2][4][4];
#pragma unroll
    for (int a = 0; a < 2; a++)
#pragma unroll
        for (int b = 0; b < 4; b++)
#pragma unroll
            for (int cc = 0; cc < 4; cc++) acc[a][b][cc] = 0.f;

    // prologue: chunks 0,1,2 into stages 0,1,2
#pragma unroll
    for (int s = 0; s < 3; s++) {
        uint32_t sb = smem0 + s * STAGE_B;
#pragma unroll
        for (int i = 0; i < 2; i++) cpa16(sb + aDst[i], aPtr[i] + s * 32);
#pragma unroll
        for (int i = 0; i < 2; i++) cpa16(sb + bDst[i], bPtr[i] + (uint32_t)(s * 32));
        asm volatile("cp.async.commit_group;\n");
    }

    for (int c = 0; c < L; ++c) {
        // publish chunk c (per-thread wait, then CTA barrier)
        if (c + 3 < L) asm volatile("cp.async.wait_group 2;\n");
        else           asm volatile("cp.async.wait_group 0;\n");
        __syncthreads();

        // refill: chunk c+3 into stage (c+3)&3 (all warps finished reading it at c-1)
        if (c + 3 < L) {
            int cn = c + 3;
            uint32_t sb = smem0 + (uint32_t)(cn & 3) * STAGE_B;
            int aOff = (cn & 15) << 5;
            uint32_t bOff = ((uint32_t)(cn >> 4) << 16) + (uint32_t)((cn & 15) << 5);
#pragma unroll
            for (int i = 0; i < 2; i++) cpa16(sb + aDst[i], aPtr[i] + aOff);
#pragma unroll
            for (int i = 0; i < 2; i++) cpa16(sb + bDst[i], bPtr[i] + bOff);
            asm volatile("cp.async.commit_group;\n");
        }

        // compute chunk c from stage c&3
        const uint32_t sb = smem0 + (uint32_t)(c & 3) * STAGE_B;
        const uint32_t aB0 = sb + aLane;
        const uint32_t bB0 = sb + bLane;
#pragma unroll
        for (int s16 = 0; s16 < 2; s16++) {
            const uint32_t aA = aB0 ^ (s16 << 5);
            const uint32_t bA = bB0 ^ (s16 << 5);
            unsigned Ah[2][4], Al[2][4];
            lm4(Ah[0], aA);          lm4(Ah[1], aA + 1024);
            lm4(Al[0], aA + 8192);   lm4(Al[1], aA + 8192 + 1024);
#pragma unroll
            for (int nn = 0; nn < 2; nn++) {
                unsigned Bh[4], Bl[4];
                lm4(Bh, bA + nn * 1024);
                lm4(Bl, bA + nn * 1024 + 8192);
#pragma unroll
                for (int mi = 0; mi < 2; mi++) {
                    mma_bf16(acc[mi][2 * nn + 0], Al[mi], Bh + 0);
                    mma_bf16(acc[mi][2 * nn + 0], Ah[mi], Bl + 0);
                    mma_bf16(acc[mi][2 * nn + 0], Ah[mi], Bh + 0);
                    mma_bf16(acc[mi][2 * nn + 1], Al[mi], Bh + 2);
                    mma_bf16(acc[mi][2 * nn + 1], Ah[mi], Bl + 2);
                    mma_bf16(acc[mi][2 * nn + 1], Ah[mi], Bh + 2);
                }
            }
        }

        // nt boundary: register-only epilogue (no smem, no barrier) + acc reset
        if ((c & 15) == 15) {
            const int nt = c >> 4;
#pragma unroll
            for (int mi = 0; mi < 2; mi++)
#pragma unroll
                for (int ni = 0; ni < 4; ni++) {
                    int col = wn * 32 + ni * 8 + 2 * t4;
                    int co  = nt * 128 + col;
                    float2 bb = __ldg(bias2 + (co >> 1));
#pragma unroll
                    for (int jr = 0; jr < 2; jr++) {
                        int row = wm * 32 + mi * 16 + g + 8 * jr;
                        float2 v;
                        v.x = acc[mi][ni][2 * jr + 0] + bb.x;
                        v.y = acc[mi][ni][2 * jr + 1] + bb.y;
                        int widx = 2 * bx + (row >> 6), rl = row & 63;
                        if (MODE == 0) {
                            int part = co >> 9, head = (co >> 5) & 15, d = co & 31;
                            float* dst = (part == 0) ? g_q : ((part == 1) ? g_k : g_v);
                            *reinterpret_cast<float2*>(
                                dst + (((size_t)(widx * 16 + head) * 64 + rl) << 5) + d) = v;
                        } else {
                            *reinterpret_cast<float2*>(out + xrow(widx, rl) * 512L + co) = v;
                        }
                    }
                }
#pragma unroll
            for (int a = 0; a < 2; a++)
#pragma unroll
                for (int b = 0; b < 4; b++)
#pragma unroll
                    for (int cc = 0; cc < 4; cc++) acc[a][b][cc] = 0.f;
        }
    }
}

// ---------------- attention (unchanged, known-good) ----------------
__global__ __launch_bounds__(128) void attn_kernel(const float* __restrict__ tbl) {
    __shared__ float sQ[64 * 36];
    __shared__ float sK[64 * 36];
    __shared__ float sV[64 * 36];
    __shared__ float sP[64 * 68];
    __shared__ float sRcp[64];

    const int bx   = blockIdx.x;
    const int widx = bx >> 4, head = bx & 15;
    const int tid  = threadIdx.x, wid = tid >> 5, lane = tid & 31;
    const int g    = lane >> 2, t4 = lane & 3;
    const size_t base = (size_t)bx * 2048;

#pragma unroll
    for (int i = 0; i < 4; i++) {
        int idx = tid + i * 128;
        int r = idx >> 3, c4 = idx & 7;
        int sb = r * 36 + c4 * 4;
        float4 q = *reinterpret_cast<const float4*>(g_q + base + (size_t)idx * 4);
        float4 k = *reinterpret_cast<const float4*>(g_k + base + (size_t)idx * 4);
        float4 v = *reinterpret_cast<const float4*>(g_v + base + (size_t)idx * 4);
        sQ[sb] = f2tf(q.x); sQ[sb + 1] = f2tf(q.y); sQ[sb + 2] = f2tf(q.z); sQ[sb + 3] = f2tf(q.w);
        sK[sb] = f2tf(k.x); sK[sb + 1] = f2tf(k.y); sK[sb + 2] = f2tf(k.z); sK[sb + 3] = f2tf(k.w);
        sV[sb] = f2tf(v.x); sV[sb + 1] = f2tf(v.y); sV[sb + 2] = f2tf(v.z); sV[sb + 3] = f2tf(v.w);
    }
    __syncthreads();

    const int r0 = wid * 16;

    float sacc[8][4];
#pragma unroll
    for (int n = 0; n < 8; n++)
#pragma unroll
        for (int j = 0; j < 4; j++) sacc[n][j] = 0.f;

#pragma unroll
    for (int ks = 0; ks < 4; ks++) {
        float a[4];
        int rr = r0 + g, c0 = ks * 8 + t4;
        a[0] = sQ[rr * 36 + c0];     a[1] = sQ[(rr + 8) * 36 + c0];
        a[2] = sQ[rr * 36 + c0 + 4]; a[3] = sQ[(rr + 8) * 36 + c0 + 4];
#pragma unroll
        for (int ni = 0; ni < 8; ni++) {
            float b[2];
            int n = ni * 8 + g;
            b[0] = sK[n * 36 + c0];
            b[1] = sK[n * 36 + c0 + 4];
            mma_tf32(sacc[ni], a, b);
        }
    }

    const float scale = 0.17677669529663687f;
#pragma unroll
    for (int ni = 0; ni < 8; ni++)
#pragma unroll
        for (int j = 0; j < 4; j++) {
            int r = r0 + g + ((j >> 1) << 3);
            int c = ni * 8 + 2 * t4 + (j & 1);
            int idx = ((r >> 3) - (c >> 3) + 7) * 15 + ((r & 7) - (c & 7) + 7);
            sP[r * 68 + c] = sacc[ni][j] * scale + __ldg(tbl + idx * 16 + head);
        }
    __syncwarp();

    {
        int r = r0 + (lane >> 1);
        int half = lane & 1;
        float* row = sP + r * 68 + half * 32;
        float m = row[0];
#pragma unroll
        for (int c = 1; c < 32; c++) m = fmaxf(m, row[c]);
        m = fmaxf(m, __shfl_xor_sync(0xffffffffu, m, 1));
        float s = 0.f;
#pragma unroll
        for (int c = 0; c < 32; c++) {
            float e = __expf(row[c] - m);
            s += e;
            row[c] = f2tf(e);
        }
        s += __shfl_xor_sync(0xffffffffu, s, 1);
        if (!half) sRcp[r] = 1.f / s;
    }
    __syncwarp();

    float oacc[4][4];
#pragma unroll
    for (int n = 0; n < 4; n++)
#pragma unroll
        for (int j = 0; j < 4; j++) oacc[n][j] = 0.f;

#pragma unroll
    for (int ks = 0; ks < 8; ks++) {
        float a[4];
        int rr = r0 + g, c0 = ks * 8 + t4;
        a[0] = sP[rr * 68 + c0];     a[1] = sP[(rr + 8) * 68 + c0];
        a[2] = sP[rr * 68 + c0 + 4]; a[3] = sP[(rr + 8) * 68 + c0 + 4];
#pragma unroll
        for (int ni = 0; ni < 4; ni++) {
            float b[2];
            b[0] = sV[c0 * 36 + ni * 8 + g];
            b[1] = sV[(c0 + 4) * 36 + ni * 8 + g];
            mma_tf32(oacc[ni], a, b);
        }
    }

#pragma unroll
    for (int ni = 0; ni < 4; ni++)
#pragma unroll
        for (int j = 0; j < 4; j++) {
            int r = r0 + g + ((j >> 1) << 3);
            int d = ni * 8 + 2 * t4 + (j & 1);
            size_t off = ((size_t)widx * 64 + r) * 512 + head * 32 + d;
            float v = oacc[ni][j] * sRcp[r];
            __nv_bfloat16 h = __float2bfloat16(v);
            g_aoh[off] = h;
            g_aol[off] = __float2bfloat16(v - __bfloat162float(h));
        }
}

// ---------------- launch ----------------
extern "C" void kernel_launch(void* const* d_in, const int* in_sizes, int n_in,
                              void* d_out, int out_size) {
    const float* x      = (const float*)d_in[0];
    const float* qkv_w  = (const float*)d_in[1];
    const float* qkv_b  = (const float*)d_in[2];
    const float* proj_w = (const float*)d_in[3];
    const float* proj_b = (const float*)d_in[4];
    const float* tbl    = (const float*)d_in[5];
    float* out = (float*)d_out;

    cudaFuncSetAttribute(gemm_lm<0>, cudaFuncAttributeMaxDynamicSharedMemorySize, GEMM_SMEM);
    cudaFuncSetAttribute(gemm_lm<1>, cudaFuncAttributeMaxDynamicSharedMemorySize, GEMM_SMEM);

    split_x_kernel<<<(NROWS * (CDIM / 4)) / 256, 256>>>(x);
    split_w_kernel<0><<<(1536 * 512) / 256, 256>>>(qkv_w);
    split_w_kernel<1><<<(512 * 512) / 256, 256>>>(proj_w);

    gemm_lm<0><<<NROWS / 128, 512, GEMM_SMEM>>>(qkv_b, nullptr);
    attn_kernel<<<NWIN * NHEADS, 128>>>(tbl);
    gemm_lm<1><<<NROWS / 128, 512, GEMM_SMEM>>>(proj_b, out);
}

// round 10
// speedup vs baseline: 2.7995x; 1.4819x over previous
#include <cuda_runtime.h>
#include <cuda_fp16.h>
#include <cstdint>

// ---------------- problem constants ----------------
#define NHEADS 16
#define CDIM   512
#define HD     32
#define NTOK   64
#define NWIN   2048
#define NROWS  (NWIN * NTOK)

// ---------------- scratch ----------------
__device__ float g_q[(size_t)NWIN * NHEADS * NTOK * HD];
__device__ float g_k[(size_t)NWIN * NHEADS * NTOK * HD];
__device__ float g_v[(size_t)NWIN * NHEADS * NTOK * HD];

// fp16 operands: A split hi/lo (exact to 2^-22), weights single fp16
__device__ __align__(256) __half g_xh[(size_t)NROWS * CDIM];
__device__ __align__(256) __half g_xl[(size_t)NROWS * CDIM];
__device__ __align__(256) __half g_aoh[(size_t)NROWS * CDIM];
__device__ __align__(256) __half g_aol[(size_t)NROWS * CDIM];
__device__ __align__(256) __half g_wt16[1536 * 512];   // qkv_w^T fp16 [n][k]
__device__ __align__(256) __half g_pt16[512 * 512];    // proj_w^T fp16 [n][k]

// ---------------- helpers ----------------
__device__ __forceinline__ float f2tf(float x) {
    unsigned u; asm("cvt.rna.tf32.f32 %0, %1;" : "=r"(u) : "f"(x));
    return __uint_as_float(u);
}
__device__ __forceinline__ void mma_tf32(float c[4], const float a[4], const float b[2]) {
    asm volatile(
        "mma.sync.aligned.m16n8k8.row.col.f32.tf32.tf32.f32 "
        "{%0,%1,%2,%3},{%4,%5,%6,%7},{%8,%9},{%0,%1,%2,%3};\n"
        : "+f"(c[0]), "+f"(c[1]), "+f"(c[2]), "+f"(c[3])
        : "r"(__float_as_uint(a[0])), "r"(__float_as_uint(a[1])),
          "r"(__float_as_uint(a[2])), "r"(__float_as_uint(a[3])),
          "r"(__float_as_uint(b[0])), "r"(__float_as_uint(b[1])));
}
__device__ __forceinline__ void mma_f16(float c[4], const unsigned a[4], const unsigned b[2]) {
    asm volatile(
        "mma.sync.aligned.m16n8k16.row.col.f32.f16.f16.f32 "
        "{%0,%1,%2,%3},{%4,%5,%6,%7},{%8,%9},{%0,%1,%2,%3};\n"
        : "+f"(c[0]), "+f"(c[1]), "+f"(c[2]), "+f"(c[3])
        : "r"(a[0]), "r"(a[1]), "r"(a[2]), "r"(a[3]), "r"(b[0]), "r"(b[1]));
}
__device__ __forceinline__ void lm4(unsigned r[4], uint32_t addr) {
    asm volatile("ldmatrix.sync.aligned.m8n8.x4.shared.b16 {%0,%1,%2,%3}, [%4];"
                 : "=r"(r[0]), "=r"(r[1]), "=r"(r[2]), "=r"(r[3]) : "r"(addr));
}
__device__ __forceinline__ void cpa16(uint32_t dst, const void* src) {
    asm volatile("cp.async.cg.shared.global [%0], [%1], 16;\n" :: "r"(dst), "l"(src));
}
__device__ __forceinline__ long xrow(int widx, int n) {
    int b  = widx >> 8;
    int hy = (widx >> 4) & 15;
    int wx = widx & 15;
    int h  = hy * 8 + (n >> 3);
    int w  = wx * 8 + (n & 7);
    return ((long)((b << 7) + h) << 7) + w;
}

// ---------------- prep kernels ----------------
__global__ __launch_bounds__(256) void split_x_kernel(const float* __restrict__ x) {
    size_t i = (size_t)blockIdx.x * 256 + threadIdx.x;
    float4 v = reinterpret_cast<const float4*>(x)[i];
    __half h0 = __float2half_rn(v.x), h1 = __float2half_rn(v.y);
    __half h2 = __float2half_rn(v.z), h3 = __float2half_rn(v.w);
    __half l0 = __float2half_rn(v.x - __half2float(h0));
    __half l1 = __float2half_rn(v.y - __half2float(h1));
    __half l2 = __float2half_rn(v.z - __half2float(h2));
    __half l3 = __float2half_rn(v.w - __half2float(h3));
    reinterpret_cast<__half2*>(g_xh)[2 * i + 0] = __halves2half2(h0, h1);
    reinterpret_cast<__half2*>(g_xh)[2 * i + 1] = __halves2half2(h2, h3);
    reinterpret_cast<__half2*>(g_xl)[2 * i + 0] = __halves2half2(l0, l1);
    reinterpret_cast<__half2*>(g_xl)[2 * i + 1] = __halves2half2(l2, l3);
}
template <int WSEL>
__global__ __launch_bounds__(256) void split_w_kernel(const float* __restrict__ W) {
    constexpr int N = (WSEL == 0) ? 1536 : 512;
    int idx = blockIdx.x * 256 + threadIdx.x;
    int n = idx >> 9, k = idx & 511;
    float v = W[(size_t)k * N + n];
    if (WSEL == 0) g_wt16[idx] = __float2half_rn(v);
    else           g_pt16[idx] = __float2half_rn(v);
}

// ---------------- fp16 2-term GEMM (A hi/lo exact, B fp16) ----------------
// CTA tile M=64 x N=128, Ktile=32, 256 threads (8 warps, 2x4, warp tile 32x32).
// FLAT 4-stage cp.async pipeline, one __syncthreads per chunk, register epilogue.
// Stage (16KB): A_hi [0,4K) A_lo [4K,8K) B [8K,16K). 64KB total -> 2-3 CTAs/SM.
// Rows 64B; 16B chunk swizzle c' = c ^ ((row>>1)&3) (conflict-free ldmatrix).
#define STAGE_B  16384
#define GEMM_SMEM (4 * STAGE_B)

template <int MODE>   // 0: QKV (NT=12), 1: proj (NT=4)
__global__ __launch_bounds__(256, 2) void gemm_lm(
    const float* __restrict__ bias, float* __restrict__ out)
{
    constexpr int NT = (MODE == 0) ? 12 : 4;
    constexpr int L  = NT * 16;
    extern __shared__ __align__(128) char dyn[];
    const uint32_t smem0 = (uint32_t)__cvta_generic_to_shared(dyn);

    const int bx   = blockIdx.x;
    const int tid  = threadIdx.x;
    const int wid  = tid >> 5, lane = tid & 31;
    const int g    = lane >> 2, t4 = lane & 3;
    const int wm   = wid & 1, wn = wid >> 1;

    const __half* APh = (MODE == 0) ? g_xh : g_aoh;
    const __half* APl = (MODE == 0) ? g_xl : g_aol;
    const __half* BP  = (MODE == 0) ? g_wt16 : g_pt16;

    // ---- cp.async tasks: 512 A (2/thread) + 512 B (2/thread), 16B each ----
    const __half* aPtr[2]; uint32_t aDst[2];
#pragma unroll
    for (int i = 0; i < 2; i++) {
        int idx = tid + i * 256;
        int row = idx >> 3, rem = idx & 7;
        int ch = rem & 3, half = rem >> 2;
        long rowb = (MODE == 0) ? xrow(bx, row) * 512L
                                : ((long)bx * 64 + row) * 512L;
        aPtr[i] = (half ? APl : APh) + rowb + ch * 8;
        aDst[i] = half * 4096u + row * 64u + (((uint32_t)(ch ^ ((row >> 1) & 3))) << 4);
    }
    const __half* bPtr[2]; uint32_t bDst[2];
#pragma unroll
    for (int i = 0; i < 2; i++) {
        int idx = tid + i * 256;
        int row = idx >> 2, ch = idx & 3;
        bPtr[i] = BP + (size_t)row * 512 + ch * 8;
        bDst[i] = 8192u + row * 64u + (((uint32_t)(ch ^ ((row >> 1) & 3))) << 4);
    }

    // ---- ldmatrix per-lane base offsets ----
    const int rowA = wm * 32 + (lane & 15);
    const int cbA  = (lane >> 4) & 1;
    const uint32_t aLane = rowA * 64u + (((uint32_t)(cbA ^ ((rowA >> 1) & 3))) << 4);
    const int rowB = wn * 32 + (lane & 7) + (((lane >> 4) & 1) << 3);
    const int cbB  = (lane >> 3) & 1;
    const uint32_t bLane = 8192u + rowB * 64u +
                           (((uint32_t)(cbB ^ ((rowB >> 1) & 3))) << 4);

    const float2* bias2 = reinterpret_cast<const float2*>(bias);

    float acc[2][4][4];
#pragma unroll
    for (int a = 0; a < 2; a++)
#pragma unroll
        for (int b = 0; b < 4; b++)
#pragma unroll
            for (int cc = 0; cc < 4; cc++) acc[a][b][cc] = 0.f;

    // prologue: chunks 0,1,2 into stages 0,1,2
#pragma unroll
    for (int s = 0; s < 3; s++) {
        uint32_t sb = smem0 + s * STAGE_B;
#pragma unroll
        for (int i = 0; i < 2; i++) cpa16(sb + aDst[i], aPtr[i] + s * 32);
#pragma unroll
        for (int i = 0; i < 2; i++) cpa16(sb + bDst[i], bPtr[i] + (uint32_t)(s * 32));
        asm volatile("cp.async.commit_group;\n");
    }

    for (int c = 0; c < L; ++c) {
        if (c + 3 < L) asm volatile("cp.async.wait_group 2;\n");
        else           asm volatile("cp.async.wait_group 0;\n");
        __syncthreads();

        // refill chunk c+3 into stage (c+3)&3
        if (c + 3 < L) {
            int cn = c + 3;
            uint32_t sb = smem0 + (uint32_t)(cn & 3) * STAGE_B;
            int aOff = (cn & 15) << 5;
            uint32_t bOff = ((uint32_t)(cn >> 4) << 16) + (uint32_t)((cn & 15) << 5);
#pragma unroll
            for (int i = 0; i < 2; i++) cpa16(sb + aDst[i], aPtr[i] + aOff);
#pragma unroll
            for (int i = 0; i < 2; i++) cpa16(sb + bDst[i], bPtr[i] + bOff);
            asm volatile("cp.async.commit_group;\n");
        }

        // compute chunk c
        const uint32_t sb = smem0 + (uint32_t)(c & 3) * STAGE_B;
        const uint32_t aB0 = sb + aLane;
        const uint32_t bB0 = sb + bLane;
#pragma unroll
        for (int s16 = 0; s16 < 2; s16++) {
            const uint32_t aA = aB0 ^ (s16 << 5);
            const uint32_t bA = bB0 ^ (s16 << 5);
            unsigned Ah[2][4], Al[2][4];
            lm4(Ah[0], aA);          lm4(Ah[1], aA + 1024);
            lm4(Al[0], aA + 4096);   lm4(Al[1], aA + 4096 + 1024);
#pragma unroll
            for (int nn = 0; nn < 2; nn++) {
                unsigned Bv[4];
                lm4(Bv, bA + nn * 1024);
#pragma unroll
                for (int mi = 0; mi < 2; mi++) {
                    mma_f16(acc[mi][2 * nn + 0], Al[mi], Bv + 0);
                    mma_f16(acc[mi][2 * nn + 0], Ah[mi], Bv + 0);
                    mma_f16(acc[mi][2 * nn + 1], Al[mi], Bv + 2);
                    mma_f16(acc[mi][2 * nn + 1], Ah[mi], Bv + 2);
                }
            }
        }

        // nt boundary: register-only epilogue + acc reset
        if ((c & 15) == 15) {
            const int nt = c >> 4;
#pragma unroll
            for (int mi = 0; mi < 2; mi++)
#pragma unroll
                for (int ni = 0; ni < 4; ni++) {
                    int col = wn * 32 + ni * 8 + 2 * t4;
                    int co  = nt * 128 + col;
                    float2 bb = __ldg(bias2 + (co >> 1));
#pragma unroll
                    for (int jr = 0; jr < 2; jr++) {
                        int row = wm * 32 + mi * 16 + g + 8 * jr;   // [0,64)
                        float2 v;
                        v.x = acc[mi][ni][2 * jr + 0] + bb.x;
                        v.y = acc[mi][ni][2 * jr + 1] + bb.y;
                        if (MODE == 0) {
                            int part = co >> 9, head = (co >> 5) & 15, d = co & 31;
                            float* dst = (part == 0) ? g_q : ((part == 1) ? g_k : g_v);
                            *reinterpret_cast<float2*>(
                                dst + (((size_t)(bx * 16 + head) * 64 + row) << 5) + d) = v;
                        } else {
                            *reinterpret_cast<float2*>(out + xrow(bx, row) * 512L + co) = v;
                        }
                    }
                }
#pragma unroll
            for (int a = 0; a < 2; a++)
#pragma unroll
                for (int b = 0; b < 4; b++)
#pragma unroll
                    for (int cc = 0; cc < 4; cc++) acc[a][b][cc] = 0.f;
        }
    }
}

// ---------------- attention (unchanged, known-good; epilogue -> fp16 hi/lo) ----
__global__ __launch_bounds__(128) void attn_kernel(const float* __restrict__ tbl) {
    __shared__ float sQ[64 * 36];
    __shared__ float sK[64 * 36];
    __shared__ float sV[64 * 36];
    __shared__ float sP[64 * 68];
    __shared__ float sRcp[64];

    const int bx   = blockIdx.x;
    const int widx = bx >> 4, head = bx & 15;
    const int tid  = threadIdx.x, wid = tid >> 5, lane = tid & 31;
    const int g    = lane >> 2, t4 = lane & 3;
    const size_t base = (size_t)bx * 2048;

#pragma unroll
    for (int i = 0; i < 4; i++) {
        int idx = tid + i * 128;
        int r = idx >> 3, c4 = idx & 7;
        int sb = r * 36 + c4 * 4;
        float4 q = *reinterpret_cast<const float4*>(g_q + base + (size_t)idx * 4);
        float4 k = *reinterpret_cast<const float4*>(g_k + base + (size_t)idx * 4);
        float4 v = *reinterpret_cast<const float4*>(g_v + base + (size_t)idx * 4);
        sQ[sb] = f2tf(q.x); sQ[sb + 1] = f2tf(q.y); sQ[sb + 2] = f2tf(q.z); sQ[sb + 3] = f2tf(q.w);
        sK[sb] = f2tf(k.x); sK[sb + 1] = f2tf(k.y); sK[sb + 2] = f2tf(k.z); sK[sb + 3] = f2tf(k.w);
        sV[sb] = f2tf(v.x); sV[sb + 1] = f2tf(v.y); sV[sb + 2] = f2tf(v.z); sV[sb + 3] = f2tf(v.w);
    }
    __syncthreads();

    const int r0 = wid * 16;

    float sacc[8][4];
#pragma unroll
    for (int n = 0; n < 8; n++)
#pragma unroll
        for (int j = 0; j < 4; j++) sacc[n][j] = 0.f;

#pragma unroll
    for (int ks = 0; ks < 4; ks++) {
        float a[4];
        int rr = r0 + g, c0 = ks * 8 + t4;
        a[0] = sQ[rr * 36 + c0];     a[1] = sQ[(rr + 8) * 36 + c0];
        a[2] = sQ[rr * 36 + c0 + 4]; a[3] = sQ[(rr + 8) * 36 + c0 + 4];
#pragma unroll
        for (int ni = 0; ni < 8; ni++) {
            float b[2];
            int n = ni * 8 + g;
            b[0] = sK[n * 36 + c0];
            b[1] = sK[n * 36 + c0 + 4];
            mma_tf32(sacc[ni], a, b);
        }
    }

    const float scale = 0.17677669529663687f;
#pragma unroll
    for (int ni = 0; ni < 8; ni++)
#pragma unroll
        for (int j = 0; j < 4; j++) {
            int r = r0 + g + ((j >> 1) << 3);
            int c = ni * 8 + 2 * t4 + (j & 1);
            int idx = ((r >> 3) - (c >> 3) + 7) * 15 + ((r & 7) - (c & 7) + 7);
            sP[r * 68 + c] = sacc[ni][j] * scale + __ldg(tbl + idx * 16 + head);
        }
    __syncwarp();

    {
        int r = r0 + (lane >> 1);
        int half = lane & 1;
        float* row = sP + r * 68 + half * 32;
        float m = row[0];
#pragma unroll
        for (int c = 1; c < 32; c++) m = fmaxf(m, row[c]);
        m = fmaxf(m, __shfl_xor_sync(0xffffffffu, m, 1));
        float s = 0.f;
#pragma unroll
        for (int c = 0; c < 32; c++) {
            float e = __expf(row[c] - m);
            s += e;
            row[c] = f2tf(e);
        }
        s += __shfl_xor_sync(0xffffffffu, s, 1);
        if (!half) sRcp[r] = 1.f / s;
    }
    __syncwarp();

    float oacc[4][4];
#pragma unroll
    for (int n = 0; n < 4; n++)
#pragma unroll
        for (int j = 0; j < 4; j++) oacc[n][j] = 0.f;

#pragma unroll
    for (int ks = 0; ks < 8; ks++) {
        float a[4];
        int rr = r0 + g, c0 = ks * 8 + t4;
        a[0] = sP[rr * 68 + c0];     a[1] = sP[(rr + 8) * 68 + c0];
        a[2] = sP[rr * 68 + c0 + 4]; a[3] = sP[(rr + 8) * 68 + c0 + 4];
#pragma unroll
        for (int ni = 0; ni < 4; ni++) {
            float b[2];
            b[0] = sV[c0 * 36 + ni * 8 + g];
            b[1] = sV[(c0 + 4) * 36 + ni * 8 + g];
            mma_tf32(oacc[ni], a, b);
        }
    }

    // epilogue: normalize, write fp16 hi/lo for the proj GEMM
#pragma unroll
    for (int ni = 0; ni < 4; ni++)
#pragma unroll
        for (int j = 0; j < 4; j++) {
            int r = r0 + g + ((j >> 1) << 3);
            int d = ni * 8 + 2 * t4 + (j & 1);
            size_t off = ((size_t)widx * 64 + r) * 512 + head * 32 + d;
            float v = oacc[ni][j] * sRcp[r];
            __half h = __float2half_rn(v);
            g_aoh[off] = h;
            g_aol[off] = __float2half_rn(v - __half2float(h));
        }
}

// ---------------- launch ----------------
extern "C" void kernel_launch(void* const* d_in, const int* in_sizes, int n_in,
                              void* d_out, int out_size) {
    const float* x      = (const float*)d_in[0];
    const float* qkv_w  = (const float*)d_in[1];
    const float* qkv_b  = (const float*)d_in[2];
    const float* proj_w = (const float*)d_in[3];
    const float* proj_b = (const float*)d_in[4];
    const float* tbl    = (const float*)d_in[5];
    float* out = (float*)d_out;

    cudaFuncSetAttribute(gemm_lm<0>, cudaFuncAttributeMaxDynamicSharedMemorySize, GEMM_SMEM);
    cudaFuncSetAttribute(gemm_lm<1>, cudaFuncAttributeMaxDynamicSharedMemorySize, GEMM_SMEM);

    split_x_kernel<<<(NROWS * (CDIM / 4)) / 256, 256>>>(x);
    split_w_kernel<0><<<(1536 * 512) / 256, 256>>>(qkv_w);
    split_w_kernel<1><<<(512 * 512) / 256, 256>>>(proj_w);

    gemm_lm<0><<<NWIN, 256, GEMM_SMEM>>>(qkv_b, nullptr);
    attn_kernel<<<NWIN * NHEADS, 128>>>(tbl);
    gemm_lm<1><<<NWIN, 256, GEMM_SMEM>>>(proj_b, out);
}

// round 12
// speedup vs baseline: 2.9898x; 1.0680x over previous
#include <cuda_runtime.h>
#include <cuda_fp16.h>
#include <cstdint>

// ---------------- problem constants ----------------
#define NHEADS 16
#define CDIM   512
#define HD     32
#define NTOK   64
#define NWIN   2048
#define NROWS  (NWIN * NTOK)

// ---------------- scratch ----------------
// per (win,head): q hi/lo fp16 [64 tok][32 d], k fp16 [64][32], v^T fp16 [32 d][64 tok]
__device__ __align__(256) __half g_qh[(size_t)NWIN * NHEADS * NTOK * HD];
__device__ __align__(256) __half g_ql[(size_t)NWIN * NHEADS * NTOK * HD];
__device__ __align__(256) __half g_k16[(size_t)NWIN * NHEADS * NTOK * HD];
__device__ __align__(256) __half g_vt[(size_t)NWIN * NHEADS * NTOK * HD];

__device__ __align__(256) __half g_xh[(size_t)NROWS * CDIM];
__device__ __align__(256) __half g_xl[(size_t)NROWS * CDIM];
__device__ __align__(256) __half g_aoh[(size_t)NROWS * CDIM];
__device__ __align__(256) __half g_aol[(size_t)NROWS * CDIM];
__device__ __align__(256) __half g_wt16[1536 * 512];   // qkv_w^T fp16 [n][k]
__device__ __align__(256) __half g_pt16[512 * 512];    // proj_w^T fp16 [n][k]

// ---------------- helpers ----------------
__device__ __forceinline__ unsigned h2u(__half2 h) {
    return *reinterpret_cast<unsigned*>(&h);
}
__device__ __forceinline__ void mma_f16(float c[4], const unsigned a[4], const unsigned b[2]) {
    asm volatile(
        "mma.sync.aligned.m16n8k16.row.col.f32.f16.f16.f32 "
        "{%0,%1,%2,%3},{%4,%5,%6,%7},{%8,%9},{%0,%1,%2,%3};\n"
        : "+f"(c[0]), "+f"(c[1]), "+f"(c[2]), "+f"(c[3])
        : "r"(a[0]), "r"(a[1]), "r"(a[2]), "r"(a[3]), "r"(b[0]), "r"(b[1]));
}
__device__ __forceinline__ void lm4(unsigned r[4], uint32_t addr) {
    asm volatile("ldmatrix.sync.aligned.m8n8.x4.shared.b16 {%0,%1,%2,%3}, [%4];"
                 : "=r"(r[0]), "=r"(r[1]), "=r"(r[2]), "=r"(r[3]) : "r"(addr));
}
__device__ __forceinline__ void cpa16(uint32_t dst, const void* src) {
    asm volatile("cp.async.cg.shared.global [%0], [%1], 16;\n" :: "r"(dst), "l"(src));
}
__device__ __forceinline__ long xrow(int widx, int n) {
    int b  = widx >> 8;
    int hy = (widx >> 4) & 15;
    int wx = widx & 15;
    int h  = hy * 8 + (n >> 3);
    int w  = wx * 8 + (n & 7);
    return ((long)((b << 7) + h) << 7) + w;
}

// ---------------- prep kernels ----------------
__global__ __launch_bounds__(256) void split_x_kernel(const float* __restrict__ x) {
    size_t i = (size_t)blockIdx.x * 256 + threadIdx.x;
    float4 v = reinterpret_cast<const float4*>(x)[i];
    __half h0 = __float2half_rn(v.x), h1 = __float2half_rn(v.y);
    __half h2 = __float2half_rn(v.z), h3 = __float2half_rn(v.w);
    __half l0 = __float2half_rn(v.x - __half2float(h0));
    __half l1 = __float2half_rn(v.y - __half2float(h1));
    __half l2 = __float2half_rn(v.z - __half2float(h2));
    __half l3 = __float2half_rn(v.w - __half2float(h3));
    reinterpret_cast<__half2*>(g_xh)[2 * i + 0] = __halves2half2(h0, h1);
    reinterpret_cast<__half2*>(g_xh)[2 * i + 1] = __halves2half2(h2, h3);
    reinterpret_cast<__half2*>(g_xl)[2 * i + 0] = __halves2half2(l0, l1);
    reinterpret_cast<__half2*>(g_xl)[2 * i + 1] = __halves2half2(l2, l3);
}
template <int WSEL>
__global__ __launch_bounds__(256) void split_w_kernel(const float* __restrict__ W) {
    constexpr int N = (WSEL == 0) ? 1536 : 512;
    int idx = blockIdx.x * 256 + threadIdx.x;
    int n = idx >> 9, k = idx & 511;
    float v = W[(size_t)k * N + n];
    if (WSEL == 0) g_wt16[idx] = __float2half_rn(v);
    else           g_pt16[idx] = __float2half_rn(v);
}

// ---------------- fp16 2-term GEMM (A hi/lo exact, B fp16) ----------------
// CTA tile M=64 x N=128, Ktile=32, 256 threads. Flat 4-stage cp.async pipeline.
#define STAGE_B  16384
#define GEMM_SMEM (4 * STAGE_B)

template <int MODE>   // 0: QKV (NT=12), 1: proj (NT=4)
__global__ __launch_bounds__(256, 2) void gemm_lm(
    const float* __restrict__ bias, float* __restrict__ out)
{
    constexpr int NT = (MODE == 0) ? 12 : 4;
    constexpr int L  = NT * 16;
    extern __shared__ __align__(128) char dyn[];
    const uint32_t smem0 = (uint32_t)__cvta_generic_to_shared(dyn);

    const int bx   = blockIdx.x;
    const int tid  = threadIdx.x;
    const int wid  = tid >> 5, lane = tid & 31;
    const int g    = lane >> 2, t4 = lane & 3;
    const int wm   = wid & 1, wn = wid >> 1;

    const __half* APh = (MODE == 0) ? g_xh : g_aoh;
    const __half* APl = (MODE == 0) ? g_xl : g_aol;
    const __half* BP  = (MODE == 0) ? g_wt16 : g_pt16;

    const __half* aPtr[2]; uint32_t aDst[2];
#pragma unroll
    for (int i = 0; i < 2; i++) {
        int idx = tid + i * 256;
        int row = idx >> 3, rem = idx & 7;
        int ch = rem & 3, half = rem >> 2;
        long rowb = (MODE == 0) ? xrow(bx, row) * 512L
                                : ((long)bx * 64 + row) * 512L;
        aPtr[i] = (half ? APl : APh) + rowb + ch * 8;
        aDst[i] = half * 4096u + row * 64u + (((uint32_t)(ch ^ ((row >> 1) & 3))) << 4);
    }
    const __half* bPtr[2]; uint32_t bDst[2];
#pragma unroll
    for (int i = 0; i < 2; i++) {
        int idx = tid + i * 256;
        int row = idx >> 2, ch = idx & 3;
        bPtr[i] = BP + (size_t)row * 512 + ch * 8;
        bDst[i] = 8192u + row * 64u + (((uint32_t)(ch ^ ((row >> 1) & 3))) << 4);
    }

    const int rowA = wm * 32 + (lane & 15);
    const int cbA  = (lane >> 4) & 1;
    const uint32_t aLane = rowA * 64u + (((uint32_t)(cbA ^ ((rowA >> 1) & 3))) << 4);
    const int rowB = wn * 32 + (lane & 7) + (((lane >> 4) & 1) << 3);
    const int cbB  = (lane >> 3) & 1;
    const uint32_t bLane = 8192u + rowB * 64u +
                           (((uint32_t)(cbB ^ ((rowB >> 1) & 3))) << 4);

    const float2* bias2 = reinterpret_cast<const float2*>(bias);

    float acc[2][4][4];
#pragma unroll
    for (int a = 0; a < 2; a++)
#pragma unroll
        for (int b = 0; b < 4; b++)
#pragma unroll
            for (int cc = 0; cc < 4; cc++) acc[a][b][cc] = 0.f;

#pragma unroll
    for (int s = 0; s < 3; s++) {
        uint32_t sb = smem0 + s * STAGE_B;
#pragma unroll
        for (int i = 0; i < 2; i++) cpa16(sb + aDst[i], aPtr[i] + s * 32);
#pragma unroll
        for (int i = 0; i < 2; i++) cpa16(sb + bDst[i], bPtr[i] + (uint32_t)(s * 32));
        asm volatile("cp.async.commit_group;\n");
    }

    for (int c = 0; c < L; ++c) {
        if (c + 3 < L) asm volatile("cp.async.wait_group 2;\n");
        else           asm volatile("cp.async.wait_group 0;\n");
        __syncthreads();

        if (c + 3 < L) {
            int cn = c + 3;
            uint32_t sb = smem0 + (uint32_t)(cn & 3) * STAGE_B;
            int aOff = (cn & 15) << 5;
            uint32_t bOff = ((uint32_t)(cn >> 4) << 16) + (uint32_t)((cn & 15) << 5);
#pragma unroll
            for (int i = 0; i < 2; i++) cpa16(sb + aDst[i], aPtr[i] + aOff);
#pragma unroll
            for (int i = 0; i < 2; i++) cpa16(sb + bDst[i], bPtr[i] + bOff);
            asm volatile("cp.async.commit_group;\n");
        }

        const uint32_t sb = smem0 + (uint32_t)(c & 3) * STAGE_B;
        const uint32_t aB0 = sb + aLane;
        const uint32_t bB0 = sb + bLane;
#pragma unroll
        for (int s16 = 0; s16 < 2; s16++) {
            const uint32_t aA = aB0 ^ (s16 << 5);
            const uint32_t bA = bB0 ^ (s16 << 5);
            unsigned Ah[2][4], Al[2][4];
            lm4(Ah[0], aA);          lm4(Ah[1], aA + 1024);
            lm4(Al[0], aA + 4096);   lm4(Al[1], aA + 4096 + 1024);
#pragma unroll
            for (int nn = 0; nn < 2; nn++) {
                unsigned Bv[4];
                lm4(Bv, bA + nn * 1024);
#pragma unroll
                for (int mi = 0; mi < 2; mi++) {
                    mma_f16(acc[mi][2 * nn + 0], Al[mi], Bv + 0);
                    mma_f16(acc[mi][2 * nn + 0], Ah[mi], Bv + 0);
                    mma_f16(acc[mi][2 * nn + 1], Al[mi], Bv + 2);
                    mma_f16(acc[mi][2 * nn + 1], Ah[mi], Bv + 2);
                }
            }
        }

        if ((c & 15) == 15) {
            const int nt = c >> 4;
#pragma unroll
            for (int mi = 0; mi < 2; mi++)
#pragma unroll
                for (int ni = 0; ni < 4; ni++) {
                    int col = wn * 32 + ni * 8 + 2 * t4;
                    int co  = nt * 128 + col;
                    float2 bb = __ldg(bias2 + (co >> 1));
#pragma unroll
                    for (int jr = 0; jr < 2; jr++) {
                        int row = wm * 32 + mi * 16 + g + 8 * jr;   // [0,64)
                        float vx = acc[mi][ni][2 * jr + 0] + bb.x;
                        float vy = acc[mi][ni][2 * jr + 1] + bb.y;
                        if (MODE == 0) {
                            int part = co >> 9, head = (co >> 5) & 15, d = co & 31;
                            size_t tokb = ((size_t)(bx * 16 + head) * 64 + row);
                            if (part == 0) {        // Q: split hi/lo fp16
                                __half hx = __float2half_rn(vx), hy = __float2half_rn(vy);
                                __half lx = __float2half_rn(vx - __half2float(hx));
                                __half ly = __float2half_rn(vy - __half2float(hy));
                                *reinterpret_cast<__half2*>(g_qh + tokb * 32 + d) =
                                    __halves2half2(hx, hy);
                                *reinterpret_cast<__half2*>(g_ql + tokb * 32 + d) =
                                    __halves2half2(lx, ly);
                            } else if (part == 1) { // K: single fp16
                                *reinterpret_cast<__half2*>(g_k16 + tokb * 32 + d) =
                                    __halves2half2(__float2half_rn(vx), __float2half_rn(vy));
                            } else {                // V: transposed [dim][tok], single fp16
                                size_t vb = (size_t)(bx * 16 + head) * 32;
                                g_vt[(vb + d) * 64 + row]     = __float2half_rn(vx);
                                g_vt[(vb + d + 1) * 64 + row] = __float2half_rn(vy);
                            }
                        } else {
                            float2 v2; v2.x = vx; v2.y = vy;
                            *reinterpret_cast<float2*>(out + xrow(bx, row) * 512L + co) = v2;
                        }
                    }
                }
#pragma unroll
            for (int a = 0; a < 2; a++)
#pragma unroll
                for (int b = 0; b < 4; b++)
#pragma unroll
                    for (int cc = 0; cc < 4; cc++) acc[a][b][cc] = 0.f;
        }
    }
}

// ---------------- attention: ldmatrix + fp16 mma ----------------
// One block per (win, head), 4 warps x 16 query rows.
// Padded smem strides (80B for 64B rows, 144B for 128B rows) put 8 consecutive
// rows on distinct 16B banks -> conflict-free ldmatrix without XOR swizzle.
#define S_QH  0u
#define S_QL  5120u
#define S_K   10240u
#define S_VT  15360u     // 32 rows x 144
#define S_PH  19968u     // 64 rows x 144
#define S_PL  29184u
#define S_RCP 38400u     // 64 floats
#define ATTN_SMEM 38656

__global__ __launch_bounds__(128) void attn_kernel(const float* __restrict__ tbl) {
    __shared__ __align__(16) char sm[ATTN_SMEM];
    const uint32_t sb = (uint32_t)__cvta_generic_to_shared(sm);
    float* sRcp = reinterpret_cast<float*>(sm + S_RCP);

    const int bx   = blockIdx.x;
    const int widx = bx >> 4, head = bx & 15;
    const int tid  = threadIdx.x, wid = tid >> 5, lane = tid & 31;
    const int g    = lane >> 2, t4 = lane & 3;

    const __half* qh = g_qh  + (size_t)bx * 2048;
    const __half* ql = g_ql  + (size_t)bx * 2048;
    const __half* kk = g_k16 + (size_t)bx * 2048;
    const __half* vt = g_vt  + (size_t)bx * 2048;

    // ---- stage 16KB via cp.async ----
#pragma unroll
    for (int i = 0; i < 8; i++) {
        int idx = i * 128 + tid;
        if (idx < 768) {
            int arr = idx >> 8;          // 0:qh 1:ql 2:k
            int rem = idx & 255;
            int row = rem >> 2, ch = rem & 3;
            const __half* src = (arr == 0 ? qh : (arr == 1 ? ql : kk)) + row * 32 + ch * 8;
            uint32_t base = (arr == 0) ? S_QH : ((arr == 1) ? S_QL : S_K);
            cpa16(sb + base + row * 80 + ch * 16, src);
        } else {
            int rem = idx - 768;
            int r = rem >> 3, ch = rem & 7;
            cpa16(sb + S_VT + r * 144 + ch * 16, vt + r * 64 + ch * 8);
        }
    }
    asm volatile("cp.async.commit_group;\ncp.async.wait_group 0;\n");
    __syncthreads();

    const int r0 = wid * 16;

    // ---- S = Q K^T (Ql*K + Qh*K) ----
    float sacc[8][4];
#pragma unroll
    for (int n = 0; n < 8; n++)
#pragma unroll
        for (int j = 0; j < 4; j++) sacc[n][j] = 0.f;

    const uint32_t aH = sb + S_QH + (r0 + (lane & 15)) * 80 + ((lane >> 4) & 1) * 16;
    const uint32_t aL = aH + (S_QL - S_QH);
    const uint32_t bK = sb + S_K + ((lane & 7) + ((lane >> 4) & 1) * 8) * 80 +
                        ((lane >> 3) & 1) * 16;
#pragma unroll
    for (int kc = 0; kc < 2; kc++) {
        unsigned Ah[4], Al[4];
        lm4(Ah, aH + kc * 32);
        lm4(Al, aL + kc * 32);
#pragma unroll
        for (int ng = 0; ng < 4; ng++) {
            unsigned Bv[4];
            lm4(Bv, bK + ng * (16 * 80) + kc * 32);
            mma_f16(sacc[2 * ng + 0], Al, Bv + 0); mma_f16(sacc[2 * ng + 0], Ah, Bv + 0);
            mma_f16(sacc[2 * ng + 1], Al, Bv + 2); mma_f16(sacc[2 * ng + 1], Ah, Bv + 2);
        }
    }

    // ---- scale + bias, register softmax (4 lanes per row; shfl over t4) ----
    const float scale = 0.17677669529663687f;
    float mx[2] = {-1e30f, -1e30f};
#pragma unroll
    for (int ni = 0; ni < 8; ni++)
#pragma unroll
        for (int j = 0; j < 4; j++) {
            int rg = r0 + g + 8 * (j >> 1);
            int c  = ni * 8 + 2 * t4 + (j & 1);
            int idx = ((rg >> 3) - (c >> 3) + 7) * 15 + ((rg & 7) - (c & 7) + 7);
            float v = sacc[ni][j] * scale + __ldg(tbl + idx * 16 + head);
            sacc[ni][j] = v;
            mx[j >> 1] = fmaxf(mx[j >> 1], v);
        }
#pragma unroll
    for (int h = 0; h < 2; h++) {
        mx[h] = fmaxf(mx[h], __shfl_xor_sync(0xffffffffu, mx[h], 1));
        mx[h] = fmaxf(mx[h], __shfl_xor_sync(0xffffffffu, mx[h], 2));
    }
    float sum[2] = {0.f, 0.f};
#pragma unroll
    for (int ni = 0; ni < 8; ni++)
#pragma unroll
        for (int j = 0; j < 4; j++) {
            float e = __expf(sacc[ni][j] - mx[j >> 1]);
            sacc[ni][j] = e;
            sum[j >> 1] += e;
        }
#pragma unroll
    for (int h = 0; h < 2; h++) {
        sum[h] += __shfl_xor_sync(0xffffffffu, sum[h], 1);
        sum[h] += __shfl_xor_sync(0xffffffffu, sum[h], 2);
    }
    if (t4 == 0) {
        sRcp[r0 + g]     = 1.f / sum[0];
        sRcp[r0 + g + 8] = 1.f / sum[1];
    }

    // ---- store P as fp16 hi/lo into smem ([row][key] A-operand layout) ----
#pragma unroll
    for (int ni = 0; ni < 8; ni++)
#pragma unroll
        for (int jr = 0; jr < 2; jr++) {
            int rg = r0 + g + 8 * jr;
            float e0 = sacc[ni][2 * jr + 0], e1 = sacc[ni][2 * jr + 1];
            __half h0 = __float2half_rn(e0), h1 = __float2half_rn(e1);
            __half l0 = __float2half_rn(e0 - __half2float(h0));
            __half l1 = __float2half_rn(e1 - __half2float(h1));
            uint32_t off = (uint32_t)rg * 144u + (uint32_t)(ni * 8 + 2 * t4) * 2u;
            unsigned ph = h2u(__halves2half2(h0, h1));
            unsigned pl = h2u(__halves2half2(l0, l1));
            asm volatile("st.shared.b32 [%0], %1;" :: "r"(sb + S_PH + off), "r"(ph) : "memory");
            asm volatile("st.shared.b32 [%0], %1;" :: "r"(sb + S_PL + off), "r"(pl) : "memory");
        }
    __syncwarp();

    // ---- O = P V (Pl*V + Ph*V), B = V^T [dim][key] ----
    float oacc[4][4];
#pragma unroll
    for (int n = 0; n < 4; n++)
#pragma unroll
        for (int j = 0; j < 4; j++) oacc[n][j] = 0.f;

    const uint32_t aP  = sb + S_PH + (r0 + (lane & 15)) * 144 + ((lane >> 4) & 1) * 16;
    const uint32_t aPl = aP + (S_PL - S_PH);
    const uint32_t bV  = sb + S_VT + ((lane & 7) + ((lane >> 4) & 1) * 8) * 144 +
                         ((lane >> 3) & 1) * 16;
#pragma unroll
    for (int kc = 0; kc < 4; kc++) {
        unsigned Ph[4], Pl[4];
        lm4(Ph, aP + kc * 32);
        lm4(Pl, aPl + kc * 32);
#pragma unroll
        for (int ng = 0; ng < 2; ng++) {
            unsigned Bv[4];
            lm4(Bv, bV + ng * (16 * 144) + kc * 32);
            mma_f16(oacc[2 * ng + 0], Pl, Bv + 0); mma_f16(oacc[2 * ng + 0], Ph, Bv + 0);
            mma_f16(oacc[2 * ng + 1], Pl, Bv + 2); mma_f16(oacc[2 * ng + 1], Ph, Bv + 2);
        }
    }

    // ---- epilogue: normalize, write fp16 hi/lo for proj GEMM ----
#pragma unroll
    for (int ni = 0; ni < 4; ni++)
#pragma unroll
        for (int jr = 0; jr < 2; jr++) {
            int rg = r0 + g + 8 * jr;
            float rcp = sRcp[rg];
            float vx = oacc[ni][2 * jr + 0] * rcp;
            float vy = oacc[ni][2 * jr + 1] * rcp;
            int d = ni * 8 + 2 * t4;
            size_t off = ((size_t)widx * 64 + rg) * 512 + head * 32 + d;
            __half hx = __float2half_rn(vx), hy = __float2half_rn(vy);
            __half lx = __float2half_rn(vx - __half2float(hx));
            __half ly = __float2half_rn(vy - __half2float(hy));
            *reinterpret_cast<__half2*>(g_aoh + off) = __halves2half2(hx, hy);
            *reinterpret_cast<__half2*>(g_aol + off) = __halves2half2(lx, ly);
        }
}

// ---------------- launch ----------------
extern "C" void kernel_launch(void* const* d_in, const int* in_sizes, int n_in,
                              void* d_out, int out_size) {
    const float* x      = (const float*)d_in[0];
    const float* qkv_w  = (const float*)d_in[1];
    const float* qkv_b  = (const float*)d_in[2];
    const float* proj_w = (const float*)d_in[3];
    const float* proj_b = (const float*)d_in[4];
    const float* tbl    = (const float*)d_in[5];
    float* out = (float*)d_out;

    cudaFuncSetAttribute(gemm_lm<0>, cudaFuncAttributeMaxDynamicSharedMemorySize, GEMM_SMEM);
    cudaFuncSetAttribute(gemm_lm<1>, cudaFuncAttributeMaxDynamicSharedMemorySize, GEMM_SMEM);

    split_x_kernel<<<(NROWS * (CDIM / 4)) / 256, 256>>>(x);
    split_w_kernel<0><<<(1536 * 512) / 256, 256>>>(qkv_w);
    split_w_kernel<1><<<(512 * 512) / 256, 256>>>(proj_w);

    gemm_lm<0><<<NWIN, 256, GEMM_SMEM>>>(qkv_b, nullptr);
    attn_kernel<<<NWIN * NHEADS, 128>>>(tbl);
    gemm_lm<1><<<NWIN, 256, GEMM_SMEM>>>(proj_b, out);
}

// round 13
// speedup vs baseline: 3.8811x; 1.2981x over previous
#include <cuda_runtime.h>
#include <cuda_fp16.h>
#include <cstdint>

// ---------------- problem constants ----------------
#define NHEADS 16
#define CDIM   512
#define HD     32
#define NTOK   64
#define NWIN   2048
#define NROWS  (NWIN * NTOK)

// ---------------- scratch ----------------
// per (win,head): q hi/lo fp16 [64 tok][32 d], k fp16 [64][32], v^T fp16 [32 d][64 tok]
__device__ __align__(256) __half g_qh[(size_t)NWIN * NHEADS * NTOK * HD];
__device__ __align__(256) __half g_ql[(size_t)NWIN * NHEADS * NTOK * HD];
__device__ __align__(256) __half g_k16[(size_t)NWIN * NHEADS * NTOK * HD];
__device__ __align__(256) __half g_vt[(size_t)NWIN * NHEADS * NTOK * HD];

__device__ __align__(256) __half g_x16[(size_t)NROWS * CDIM];   // x fp16 (single)
__device__ __align__(256) __half g_aoh[(size_t)NROWS * CDIM];   // attn out hi
__device__ __align__(256) __half g_aol[(size_t)NROWS * CDIM];   // attn out lo
__device__ __align__(256) __half g_wt16[1536 * 512];   // qkv_w^T fp16 [n][k]
__device__ __align__(256) __half g_pt16[512 * 512];    // proj_w^T fp16 [n][k]

// ---------------- helpers ----------------
__device__ __forceinline__ unsigned h2u(__half2 h) {
    return *reinterpret_cast<unsigned*>(&h);
}
__device__ __forceinline__ void mma_f16(float c[4], const unsigned a[4], const unsigned b[2]) {
    asm volatile(
        "mma.sync.aligned.m16n8k16.row.col.f32.f16.f16.f32 "
        "{%0,%1,%2,%3},{%4,%5,%6,%7},{%8,%9},{%0,%1,%2,%3};\n"
        : "+f"(c[0]), "+f"(c[1]), "+f"(c[2]), "+f"(c[3])
        : "r"(a[0]), "r"(a[1]), "r"(a[2]), "r"(a[3]), "r"(b[0]), "r"(b[1]));
}
__device__ __forceinline__ void lm4(unsigned r[4], uint32_t addr) {
    asm volatile("ldmatrix.sync.aligned.m8n8.x4.shared.b16 {%0,%1,%2,%3}, [%4];"
                 : "=r"(r[0]), "=r"(r[1]), "=r"(r[2]), "=r"(r[3]) : "r"(addr));
}
__device__ __forceinline__ void cpa16(uint32_t dst, const void* src) {
    asm volatile("cp.async.cg.shared.global [%0], [%1], 16;\n" :: "r"(dst), "l"(src));
}
__device__ __forceinline__ long xrow(int widx, int n) {
    int b  = widx >> 8;
    int hy = (widx >> 4) & 15;
    int wx = widx & 15;
    int h  = hy * 8 + (n >> 3);
    int w  = wx * 8 + (n & 7);
    return ((long)((b << 7) + h) << 7) + w;
}

// ---------------- prep kernels ----------------
__global__ __launch_bounds__(256) void split_x_kernel(const float* __restrict__ x) {
    size_t i = (size_t)blockIdx.x * 256 + threadIdx.x;
    float4 v = reinterpret_cast<const float4*>(x)[i];
    reinterpret_cast<__half2*>(g_x16)[2 * i + 0] =
        __halves2half2(__float2half_rn(v.x), __float2half_rn(v.y));
    reinterpret_cast<__half2*>(g_x16)[2 * i + 1] =
        __halves2half2(__float2half_rn(v.z), __float2half_rn(v.w));
}
template <int WSEL>
__global__ __launch_bounds__(256) void split_w_kernel(const float* __restrict__ W) {
    constexpr int N = (WSEL == 0) ? 1536 : 512;
    int idx = blockIdx.x * 256 + threadIdx.x;
    int n = idx >> 9, k = idx & 511;
    float v = W[(size_t)k * N + n];
    if (WSEL == 0) g_wt16[idx] = __float2half_rn(v);
    else           g_pt16[idx] = __float2half_rn(v);
}

// ---------------- fp16 GEMM ----------------
// MODE 0 (QKV): A single-term fp16 (x), 1 mma/acc.  Stage 12KB: A[0,4K) B[4K,12K)
// MODE 1 (proj): A hi/lo 2-term (exact), 2 mma/acc. Stage 16KB: Ah[0,4K) Al[4K,8K) B[8K,16K)
// CTA tile M=64 x N=128, Ktile=32, 256 threads. Flat 4-stage cp.async pipeline.
template <int MODE>
__global__ __launch_bounds__(256, 2) void gemm_lm(
    const float* __restrict__ bias, float* __restrict__ out)
{
    constexpr int NT      = (MODE == 0) ? 12 : 4;
    constexpr int L       = NT * 16;
    constexpr int ATERMS  = (MODE == 0) ? 1 : 2;
    constexpr uint32_t STAGE = (MODE == 0) ? 12288u : 16384u;
    constexpr uint32_t BOFF  = (MODE == 0) ? 4096u  : 8192u;

    extern __shared__ __align__(128) char dyn[];
    const uint32_t smem0 = (uint32_t)__cvta_generic_to_shared(dyn);

    const int bx   = blockIdx.x;
    const int tid  = threadIdx.x;
    const int wid  = tid >> 5, lane = tid & 31;
    const int g    = lane >> 2, t4 = lane & 3;
    const int wm   = wid & 1, wn = wid >> 1;

    const __half* APh = (MODE == 0) ? g_x16 : g_aoh;
    const __half* APl = (MODE == 0) ? g_x16 : g_aol;   // unused in MODE 0
    const __half* BP  = (MODE == 0) ? g_wt16 : g_pt16;

    // ---- cp.async tasks ----
    // A: MODE0 256 tasks (1/thread); MODE1 512 tasks (2/thread). B: 512 tasks (2/thread).
    const __half* aPtr[ATERMS]; uint32_t aDst[ATERMS];
#pragma unroll
    for (int i = 0; i < ATERMS; i++) {
        int idx = tid + i * 256;
        int row, ch, half;
        if (MODE == 0) { row = idx >> 2; ch = idx & 3; half = 0; }
        else           { row = idx >> 3; ch = idx & 3; half = (idx >> 2) & 1; }
        long rowb = (MODE == 0) ? xrow(bx, row) * 512L
                                : ((long)bx * 64 + row) * 512L;
        aPtr[i] = (half ? APl : APh) + rowb + ch * 8;
        aDst[i] = (uint32_t)half * 4096u + row * 64u +
                  (((uint32_t)(ch ^ ((row >> 1) & 3))) << 4);
    }
    const __half* bPtr[2]; uint32_t bDst[2];
#pragma unroll
    for (int i = 0; i < 2; i++) {
        int idx = tid + i * 256;
        int row = idx >> 2, ch = idx & 3;
        bPtr[i] = BP + (size_t)row * 512 + ch * 8;
        bDst[i] = BOFF + row * 64u + (((uint32_t)(ch ^ ((row >> 1) & 3))) << 4);
    }

    // ---- ldmatrix per-lane base offsets ----
    const int rowA = wm * 32 + (lane & 15);
    const int cbA  = (lane >> 4) & 1;
    const uint32_t aLane = rowA * 64u + (((uint32_t)(cbA ^ ((rowA >> 1) & 3))) << 4);
    const int rowB = wn * 32 + (lane & 7) + (((lane >> 4) & 1) << 3);
    const int cbB  = (lane >> 3) & 1;
    const uint32_t bLane = BOFF + rowB * 64u +
                           (((uint32_t)(cbB ^ ((rowB >> 1) & 3))) << 4);

    const float2* bias2 = reinterpret_cast<const float2*>(bias);

    float acc[2][4][4];
#pragma unroll
    for (int a = 0; a < 2; a++)
#pragma unroll
        for (int b = 0; b < 4; b++)
#pragma unroll
            for (int cc = 0; cc < 4; cc++) acc[a][b][cc] = 0.f;

    // prologue: chunks 0,1,2 into stages 0,1,2
#pragma unroll
    for (int s = 0; s < 3; s++) {
        uint32_t sb = smem0 + s * STAGE;
#pragma unroll
        for (int i = 0; i < ATERMS; i++) cpa16(sb + aDst[i], aPtr[i] + s * 32);
#pragma unroll
        for (int i = 0; i < 2; i++) cpa16(sb + bDst[i], bPtr[i] + (uint32_t)(s * 32));
        asm volatile("cp.async.commit_group;\n");
    }

    for (int c = 0; c < L; ++c) {
        if (c + 3 < L) asm volatile("cp.async.wait_group 2;\n");
        else           asm volatile("cp.async.wait_group 0;\n");
        __syncthreads();

        // refill chunk c+3 into stage (c+3)&3
        if (c + 3 < L) {
            int cn = c + 3;
            uint32_t sb = smem0 + (uint32_t)(cn & 3) * STAGE;
            int aOff = (cn & 15) << 5;
            uint32_t bOff = ((uint32_t)(cn >> 4) << 16) + (uint32_t)((cn & 15) << 5);
#pragma unroll
            for (int i = 0; i < ATERMS; i++) cpa16(sb + aDst[i], aPtr[i] + aOff);
#pragma unroll
            for (int i = 0; i < 2; i++) cpa16(sb + bDst[i], bPtr[i] + bOff);
            asm volatile("cp.async.commit_group;\n");
        }

        // compute chunk c
        const uint32_t sb = smem0 + (uint32_t)(c & 3) * STAGE;
        const uint32_t aB0 = sb + aLane;
        const uint32_t bB0 = sb + bLane;
#pragma unroll
        for (int s16 = 0; s16 < 2; s16++) {
            const uint32_t aA = aB0 ^ (s16 << 5);
            const uint32_t bA = bB0 ^ (s16 << 5);
            unsigned Ah[2][4], Al[2][4];
            lm4(Ah[0], aA);          lm4(Ah[1], aA + 1024);
            if (MODE == 1) {
                lm4(Al[0], aA + 4096);   lm4(Al[1], aA + 4096 + 1024);
            }
#pragma unroll
            for (int nn = 0; nn < 2; nn++) {
                unsigned Bv[4];
                lm4(Bv, bA + nn * 1024);
#pragma unroll
                for (int mi = 0; mi < 2; mi++) {
                    if (MODE == 1) {
                        mma_f16(acc[mi][2 * nn + 0], Al[mi], Bv + 0);
                        mma_f16(acc[mi][2 * nn + 1], Al[mi], Bv + 2);
                    }
                    mma_f16(acc[mi][2 * nn + 0], Ah[mi], Bv + 0);
                    mma_f16(acc[mi][2 * nn + 1], Ah[mi], Bv + 2);
                }
            }
        }

        // nt boundary: register-only epilogue + acc reset
        if ((c & 15) == 15) {
            const int nt = c >> 4;
#pragma unroll
            for (int mi = 0; mi < 2; mi++)
#pragma unroll
                for (int ni = 0; ni < 4; ni++) {
                    int col = wn * 32 + ni * 8 + 2 * t4;
                    int co  = nt * 128 + col;
                    float2 bb = __ldg(bias2 + (co >> 1));
#pragma unroll
                    for (int jr = 0; jr < 2; jr++) {
                        int row = wm * 32 + mi * 16 + g + 8 * jr;   // [0,64)
                        float vx = acc[mi][ni][2 * jr + 0] + bb.x;
                        float vy = acc[mi][ni][2 * jr + 1] + bb.y;
                        if (MODE == 0) {
                            int part = co >> 9, head = (co >> 5) & 15, d = co & 31;
                            size_t tokb = ((size_t)(bx * 16 + head) * 64 + row);
                            if (part == 0) {        // Q: split hi/lo fp16
                                __half hx = __float2half_rn(vx), hy = __float2half_rn(vy);
                                __half lx = __float2half_rn(vx - __half2float(hx));
                                __half ly = __float2half_rn(vy - __half2float(hy));
                                *reinterpret_cast<__half2*>(g_qh + tokb * 32 + d) =
                                    __halves2half2(hx, hy);
                                *reinterpret_cast<__half2*>(g_ql + tokb * 32 + d) =
                                    __halves2half2(lx, ly);
                            } else if (part == 1) { // K: single fp16
                                *reinterpret_cast<__half2*>(g_k16 + tokb * 32 + d) =
                                    __halves2half2(__float2half_rn(vx), __float2half_rn(vy));
                            } else {                // V: transposed [dim][tok], single fp16
                                size_t vb = (size_t)(bx * 16 + head) * 32;
                                g_vt[(vb + d) * 64 + row]     = __float2half_rn(vx);
                                g_vt[(vb + d + 1) * 64 + row] = __float2half_rn(vy);
                            }
                        } else {
                            float2 v2; v2.x = vx; v2.y = vy;
                            *reinterpret_cast<float2*>(out + xrow(bx, row) * 512L + co) = v2;
                        }
                    }
                }
#pragma unroll
            for (int a = 0; a < 2; a++)
#pragma unroll
                for (int b = 0; b < 4; b++)
#pragma unroll
                    for (int cc = 0; cc < 4; cc++) acc[a][b][cc] = 0.f;
        }
    }
}

// ---------------- attention: ldmatrix + fp16 mma (unchanged from R12) ----------------
#define S_QH  0u
#define S_QL  5120u
#define S_K   10240u
#define S_VT  15360u     // 32 rows x 144
#define S_PH  19968u     // 64 rows x 144
#define S_PL  29184u
#define S_RCP 38400u     // 64 floats
#define ATTN_SMEM 38656

__global__ __launch_bounds__(128) void attn_kernel(const float* __restrict__ tbl) {
    __shared__ __align__(16) char sm[ATTN_SMEM];
    const uint32_t sb = (uint32_t)__cvta_generic_to_shared(sm);
    float* sRcp = reinterpret_cast<float*>(sm + S_RCP);

    const int bx   = blockIdx.x;
    const int widx = bx >> 4, head = bx & 15;
    const int tid  = threadIdx.x, wid = tid >> 5, lane = tid & 31;
    const int g    = lane >> 2, t4 = lane & 3;

    const __half* qh = g_qh  + (size_t)bx * 2048;
    const __half* ql = g_ql  + (size_t)bx * 2048;
    const __half* kk = g_k16 + (size_t)bx * 2048;
    const __half* vt = g_vt  + (size_t)bx * 2048;

#pragma unroll
    for (int i = 0; i < 8; i++) {
        int idx = i * 128 + tid;
        if (idx < 768) {
            int arr = idx >> 8;          // 0:qh 1:ql 2:k
            int rem = idx & 255;
            int row = rem >> 2, ch = rem & 3;
            const __half* src = (arr == 0 ? qh : (arr == 1 ? ql : kk)) + row * 32 + ch * 8;
            uint32_t base = (arr == 0) ? S_QH : ((arr == 1) ? S_QL : S_K);
            cpa16(sb + base + row * 80 + ch * 16, src);
        } else {
            int rem = idx - 768;
            int r = rem >> 3, ch = rem & 7;
            cpa16(sb + S_VT + r * 144 + ch * 16, vt + r * 64 + ch * 8);
        }
    }
    asm volatile("cp.async.commit_group;\ncp.async.wait_group 0;\n");
    __syncthreads();

    const int r0 = wid * 16;

    float sacc[8][4];
#pragma unroll
    for (int n = 0; n < 8; n++)
#pragma unroll
        for (int j = 0; j < 4; j++) sacc[n][j] = 0.f;

    const uint32_t aH = sb + S_QH + (r0 + (lane & 15)) * 80 + ((lane >> 4) & 1) * 16;
    const uint32_t aL = aH + (S_QL - S_QH);
    const uint32_t bK = sb + S_K + ((lane & 7) + ((lane >> 4) & 1) * 8) * 80 +
                        ((lane >> 3) & 1) * 16;
#pragma unroll
    for (int kc = 0; kc < 2; kc++) {
        unsigned Ah[4], Al[4];
        lm4(Ah, aH + kc * 32);
        lm4(Al, aL + kc * 32);
#pragma unroll
        for (int ng = 0; ng < 4; ng++) {
            unsigned Bv[4];
            lm4(Bv, bK + ng * (16 * 80) + kc * 32);
            mma_f16(sacc[2 * ng + 0], Al, Bv + 0); mma_f16(sacc[2 * ng + 0], Ah, Bv + 0);
            mma_f16(sacc[2 * ng + 1], Al, Bv + 2); mma_f16(sacc[2 * ng + 1], Ah, Bv + 2);
        }
    }

    const float scale = 0.17677669529663687f;
    float mx[2] = {-1e30f, -1e30f};
#pragma unroll
    for (int ni = 0; ni < 8; ni++)
#pragma unroll
        for (int j = 0; j < 4; j++) {
            int rg = r0 + g + 8 * (j >> 1);
            int c  = ni * 8 + 2 * t4 + (j & 1);
            int idx = ((rg >> 3) - (c >> 3) + 7) * 15 + ((rg & 7) - (c & 7) + 7);
            float v = sacc[ni][j] * scale + __ldg(tbl + idx * 16 + head);
            sacc[ni][j] = v;
            mx[j >> 1] = fmaxf(mx[j >> 1], v);
        }
#pragma unroll
    for (int h = 0; h < 2; h++) {
        mx[h] = fmaxf(mx[h], __shfl_xor_sync(0xffffffffu, mx[h], 1));
        mx[h] = fmaxf(mx[h], __shfl_xor_sync(0xffffffffu, mx[h], 2));
    }
    float sum[2] = {0.f, 0.f};
#pragma unroll
    for (int ni = 0; ni < 8; ni++)
#pragma unroll
        for (int j = 0; j < 4; j++) {
            float e = __expf(sacc[ni][j] - mx[j >> 1]);
            sacc[ni][j] = e;
            sum[j >> 1] += e;
        }
#pragma unroll
    for (int h = 0; h < 2; h++) {
        sum[h] += __shfl_xor_sync(0xffffffffu, sum[h], 1);
        sum[h] += __shfl_xor_sync(0xffffffffu, sum[h], 2);
    }
    if (t4 == 0) {
        sRcp[r0 + g]     = 1.f / sum[0];
        sRcp[r0 + g + 8] = 1.f / sum[1];
    }

#pragma unroll
    for (int ni = 0; ni < 8; ni++)
#pragma unroll
        for (int jr = 0; jr < 2; jr++) {
            int rg = r0 + g + 8 * jr;
            float e0 = sacc[ni][2 * jr + 0], e1 = sacc[ni][2 * jr + 1];
            __half h0 = __float2half_rn(e0), h1 = __float2half_rn(e1);
            __half l0 = __float2half_rn(e0 - __half2float(h0));
            __half l1 = __float2half_rn(e1 - __half2float(h1));
            uint32_t off = (uint32_t)rg * 144u + (uint32_t)(ni * 8 + 2 * t4) * 2u;
            unsigned ph = h2u(__halves2half2(h0, h1));
            unsigned pl = h2u(__halves2half2(l0, l1));
            asm volatile("st.shared.b32 [%0], %1;" :: "r"(sb + S_PH + off), "r"(ph) : "memory");
            asm volatile("st.shared.b32 [%0], %1;" :: "r"(sb + S_PL + off), "r"(pl) : "memory");
        }
    __syncwarp();

    float oacc[4][4];
#pragma unroll
    for (int n = 0; n < 4; n++)
#pragma unroll
        for (int j = 0; j < 4; j++) oacc[n][j] = 0.f;

    const uint32_t aP  = sb + S_PH + (r0 + (lane & 15)) * 144 + ((lane >> 4) & 1) * 16;
    const uint32_t aPl = aP + (S_PL - S_PH);
    const uint32_t bV  = sb + S_VT + ((lane & 7) + ((lane >> 4) & 1) * 8) * 144 +
                         ((lane >> 3) & 1) * 16;
#pragma unroll
    for (int kc = 0; kc < 4; kc++) {
        unsigned Ph[4], Pl[4];
        lm4(Ph, aP + kc * 32);
        lm4(Pl, aPl + kc * 32);
#pragma unroll
        for (int ng = 0; ng < 2; ng++) {
            unsigned Bv[4];
            lm4(Bv, bV + ng * (16 * 144) + kc * 32);
            mma_f16(oacc[2 * ng + 0], Pl, Bv + 0); mma_f16(oacc[2 * ng + 0], Ph, Bv + 0);
            mma_f16(oacc[2 * ng + 1], Pl, Bv + 2); mma_f16(oacc[2 * ng + 1], Ph, Bv + 2);
        }
    }

#pragma unroll
    for (int ni = 0; ni < 4; ni++)
#pragma unroll
        for (int jr = 0; jr < 2; jr++) {
            int rg = r0 + g + 8 * jr;
            float rcp = sRcp[rg];
            float vx = oacc[ni][2 * jr + 0] * rcp;
            float vy = oacc[ni][2 * jr + 1] * rcp;
            int d = ni * 8 + 2 * t4;
            size_t off = ((size_t)widx * 64 + rg) * 512 + head * 32 + d;
            __half hx = __float2half_rn(vx), hy = __float2half_rn(vy);
            __half lx = __float2half_rn(vx - __half2float(hx));
            __half ly = __float2half_rn(vy - __half2float(hy));
            *reinterpret_cast<__half2*>(g_aoh + off) = __halves2half2(hx, hy);
            *reinterpret_cast<__half2*>(g_aol + off) = __halves2half2(lx, ly);
        }
}

// ---------------- launch ----------------
extern "C" void kernel_launch(void* const* d_in, const int* in_sizes, int n_in,
                              void* d_out, int out_size) {
    const float* x      = (const float*)d_in[0];
    const float* qkv_w  = (const float*)d_in[1];
    const float* qkv_b  = (const float*)d_in[2];
    const float* proj_w = (const float*)d_in[3];
    const float* proj_b = (const float*)d_in[4];
    const float* tbl    = (const float*)d_in[5];
    float* out = (float*)d_out;

    cudaFuncSetAttribute(gemm_lm<0>, cudaFuncAttributeMaxDynamicSharedMemorySize, 4 * 12288);
    cudaFuncSetAttribute(gemm_lm<1>, cudaFuncAttributeMaxDynamicSharedMemorySize, 4 * 16384);

    split_x_kernel<<<(NROWS * (CDIM / 4)) / 256, 256>>>(x);
    split_w_kernel<0><<<(1536 * 512) / 256, 256>>>(qkv_w);
    split_w_kernel<1><<<(512 * 512) / 256, 256>>>(proj_w);

    gemm_lm<0><<<NWIN, 256, 4 * 12288>>>(qkv_b, nullptr);
    attn_kernel<<<NWIN * NHEADS, 128>>>(tbl);
    gemm_lm<1><<<NWIN, 256, 4 * 16384>>>(proj_b, out);
}

// round 14
// speedup vs baseline: 4.6520x; 1.1986x over previous
#include <cuda_runtime.h>
#include <cuda_fp16.h>
#include <cstdint>

// ---------------- problem constants ----------------
#define NHEADS 16
#define CDIM   512
#define HD     32
#define NTOK   64
#define NWIN   2048
#define NROWS  (NWIN * NTOK)

// ---------------- scratch ----------------
// per (win,head): q fp16 [64 tok][32 d], k fp16 [64][32], v^T fp16 [32 d][64 tok]
__device__ __align__(256) __half g_q16[(size_t)NWIN * NHEADS * NTOK * HD];
__device__ __align__(256) __half g_k16[(size_t)NWIN * NHEADS * NTOK * HD];
__device__ __align__(256) __half g_vt[(size_t)NWIN * NHEADS * NTOK * HD];

__device__ __align__(256) __half g_x16[(size_t)NROWS * CDIM];   // x fp16
__device__ __align__(256) __half g_ao16[(size_t)NROWS * CDIM];  // attn out fp16
__device__ __align__(256) __half g_wt16[1536 * 512];   // qkv_w^T fp16 [n][k]
__device__ __align__(256) __half g_pt16[512 * 512];    // proj_w^T fp16 [n][k]

// ---------------- helpers ----------------
__device__ __forceinline__ unsigned h2u(__half2 h) {
    return *reinterpret_cast<unsigned*>(&h);
}
__device__ __forceinline__ void mma_f16(float c[4], const unsigned a[4], const unsigned b[2]) {
    asm volatile(
        "mma.sync.aligned.m16n8k16.row.col.f32.f16.f16.f32 "
        "{%0,%1,%2,%3},{%4,%5,%6,%7},{%8,%9},{%0,%1,%2,%3};\n"
        : "+f"(c[0]), "+f"(c[1]), "+f"(c[2]), "+f"(c[3])
        : "r"(a[0]), "r"(a[1]), "r"(a[2]), "r"(a[3]), "r"(b[0]), "r"(b[1]));
}
__device__ __forceinline__ void lm4(unsigned r[4], uint32_t addr) {
    asm volatile("ldmatrix.sync.aligned.m8n8.x4.shared.b16 {%0,%1,%2,%3}, [%4];"
                 : "=r"(r[0]), "=r"(r[1]), "=r"(r[2]), "=r"(r[3]) : "r"(addr));
}
__device__ __forceinline__ void cpa16(uint32_t dst, const void* src) {
    asm volatile("cp.async.cg.shared.global [%0], [%1], 16;\n" :: "r"(dst), "l"(src));
}
__device__ __forceinline__ long xrow(int widx, int n) {
    int b  = widx >> 8;
    int hy = (widx >> 4) & 15;
    int wx = widx & 15;
    int h  = hy * 8 + (n >> 3);
    int w  = wx * 8 + (n & 7);
    return ((long)((b << 7) + h) << 7) + w;
}

// ---------------- prep kernels ----------------
__global__ __launch_bounds__(256) void split_x_kernel(const float* __restrict__ x) {
    size_t i = (size_t)blockIdx.x * 256 + threadIdx.x;
    float4 v = reinterpret_cast<const float4*>(x)[i];
    reinterpret_cast<__half2*>(g_x16)[2 * i + 0] =
        __halves2half2(__float2half_rn(v.x), __float2half_rn(v.y));
    reinterpret_cast<__half2*>(g_x16)[2 * i + 1] =
        __halves2half2(__float2half_rn(v.z), __float2half_rn(v.w));
}
template <int WSEL>
__global__ __launch_bounds__(256) void split_w_kernel(const float* __restrict__ W) {
    constexpr int N = (WSEL == 0) ? 1536 : 512;
    int idx = blockIdx.x * 256 + threadIdx.x;
    int n = idx >> 9, k = idx & 511;
    float v = W[(size_t)k * N + n];
    if (WSEL == 0) g_wt16[idx] = __float2half_rn(v);
    else           g_pt16[idx] = __float2half_rn(v);
}

// ---------------- fp16 single-term GEMM ----------------
// CTA tile M=64 x N=128, Ktile=32, 256 threads (8 warps 2x4, warp tile 32x32).
// Flat 4-stage cp.async pipeline. Stage 12KB: A [0,4K) B [4K,12K).
#define STAGE_B 12288u
#define GEMM_SMEM (4 * 12288)

template <int MODE>   // 0: QKV (NT=12), 1: proj (NT=4)
__global__ __launch_bounds__(256, 2) void gemm_lm(
    const float* __restrict__ bias, float* __restrict__ out)
{
    constexpr int NT = (MODE == 0) ? 12 : 4;
    constexpr int L  = NT * 16;

    extern __shared__ __align__(128) char dyn[];
    const uint32_t smem0 = (uint32_t)__cvta_generic_to_shared(dyn);

    const int bx   = blockIdx.x;
    const int tid  = threadIdx.x;
    const int wid  = tid >> 5, lane = tid & 31;
    const int g    = lane >> 2, t4 = lane & 3;
    const int wm   = wid & 1, wn = wid >> 1;

    const __half* AP = (MODE == 0) ? g_x16 : g_ao16;
    const __half* BP = (MODE == 0) ? g_wt16 : g_pt16;

    // ---- cp.async tasks: 256 A (1/thread) + 512 B (2/thread), 16B each ----
    const __half* aPtr; uint32_t aDst;
    {
        int row = tid >> 2, ch = tid & 3;
        long rowb = (MODE == 0) ? xrow(bx, row) * 512L
                                : ((long)bx * 64 + row) * 512L;
        aPtr = AP + rowb + ch * 8;
        aDst = row * 64u + (((uint32_t)(ch ^ ((row >> 1) & 3))) << 4);
    }
    const __half* bPtr[2]; uint32_t bDst[2];
#pragma unroll
    for (int i = 0; i < 2; i++) {
        int idx = tid + i * 256;
        int row = idx >> 2, ch = idx & 3;
        bPtr[i] = BP + (size_t)row * 512 + ch * 8;
        bDst[i] = 4096u + row * 64u + (((uint32_t)(ch ^ ((row >> 1) & 3))) << 4);
    }

    // ---- ldmatrix per-lane base offsets ----
    const int rowA = wm * 32 + (lane & 15);
    const int cbA  = (lane >> 4) & 1;
    const uint32_t aLane = rowA * 64u + (((uint32_t)(cbA ^ ((rowA >> 1) & 3))) << 4);
    const int rowB = wn * 32 + (lane & 7) + (((lane >> 4) & 1) << 3);
    const int cbB  = (lane >> 3) & 1;
    const uint32_t bLane = 4096u + rowB * 64u +
                           (((uint32_t)(cbB ^ ((rowB >> 1) & 3))) << 4);

    const float2* bias2 = reinterpret_cast<const float2*>(bias);

    float acc[2][4][4];
#pragma unroll
    for (int a = 0; a < 2; a++)
#pragma unroll
        for (int b = 0; b < 4; b++)
#pragma unroll
            for (int cc = 0; cc < 4; cc++) acc[a][b][cc] = 0.f;

    // prologue: chunks 0,1,2 into stages 0,1,2
#pragma unroll
    for (int s = 0; s < 3; s++) {
        uint32_t sb = smem0 + s * STAGE_B;
        cpa16(sb + aDst, aPtr + s * 32);
#pragma unroll
        for (int i = 0; i < 2; i++) cpa16(sb + bDst[i], bPtr[i] + (uint32_t)(s * 32));
        asm volatile("cp.async.commit_group;\n");
    }

    for (int c = 0; c < L; ++c) {
        if (c + 3 < L) asm volatile("cp.async.wait_group 2;\n");
        else           asm volatile("cp.async.wait_group 0;\n");
        __syncthreads();

        if (c + 3 < L) {
            int cn = c + 3;
            uint32_t sb = smem0 + (uint32_t)(cn & 3) * STAGE_B;
            int aOff = (cn & 15) << 5;
            uint32_t bOff = ((uint32_t)(cn >> 4) << 16) + (uint32_t)((cn & 15) << 5);
            cpa16(sb + aDst, aPtr + aOff);
#pragma unroll
            for (int i = 0; i < 2; i++) cpa16(sb + bDst[i], bPtr[i] + bOff);
            asm volatile("cp.async.commit_group;\n");
        }

        const uint32_t sb = smem0 + (uint32_t)(c & 3) * STAGE_B;
        const uint32_t aB0 = sb + aLane;
        const uint32_t bB0 = sb + bLane;
#pragma unroll
        for (int s16 = 0; s16 < 2; s16++) {
            const uint32_t aA = aB0 ^ (s16 << 5);
            const uint32_t bA = bB0 ^ (s16 << 5);
            unsigned Ah[2][4];
            lm4(Ah[0], aA);          lm4(Ah[1], aA + 1024);
#pragma unroll
            for (int nn = 0; nn < 2; nn++) {
                unsigned Bv[4];
                lm4(Bv, bA + nn * 1024);
#pragma unroll
                for (int mi = 0; mi < 2; mi++) {
                    mma_f16(acc[mi][2 * nn + 0], Ah[mi], Bv + 0);
                    mma_f16(acc[mi][2 * nn + 1], Ah[mi], Bv + 2);
                }
            }
        }

        // nt boundary: register-only epilogue + acc reset
        if ((c & 15) == 15) {
            const int nt = c >> 4;
#pragma unroll
            for (int mi = 0; mi < 2; mi++)
#pragma unroll
                for (int ni = 0; ni < 4; ni++) {
                    int col = wn * 32 + ni * 8 + 2 * t4;
                    int co  = nt * 128 + col;
                    float2 bb = __ldg(bias2 + (co >> 1));
#pragma unroll
                    for (int jr = 0; jr < 2; jr++) {
                        int row = wm * 32 + mi * 16 + g + 8 * jr;   // [0,64)
                        float vx = acc[mi][ni][2 * jr + 0] + bb.x;
                        float vy = acc[mi][ni][2 * jr + 1] + bb.y;
                        if (MODE == 0) {
                            int part = co >> 9, head = (co >> 5) & 15, d = co & 31;
                            size_t tokb = ((size_t)(bx * 16 + head) * 64 + row);
                            __half hx = __float2half_rn(vx), hy = __float2half_rn(vy);
                            if (part == 0) {
                                *reinterpret_cast<__half2*>(g_q16 + tokb * 32 + d) =
                                    __halves2half2(hx, hy);
                            } else if (part == 1) {
                                *reinterpret_cast<__half2*>(g_k16 + tokb * 32 + d) =
                                    __halves2half2(hx, hy);
                            } else {                // V: transposed [dim][tok]
                                size_t vb = (size_t)(bx * 16 + head) * 32;
                                g_vt[(vb + d) * 64 + row]     = hx;
                                g_vt[(vb + d + 1) * 64 + row] = hy;
                            }
                        } else {
                            float2 v2; v2.x = vx; v2.y = vy;
                            *reinterpret_cast<float2*>(out + xrow(bx, row) * 512L + co) = v2;
                        }
                    }
                }
#pragma unroll
            for (int a = 0; a < 2; a++)
#pragma unroll
                for (int b = 0; b < 4; b++)
#pragma unroll
                    for (int cc = 0; cc < 4; cc++) acc[a][b][cc] = 0.f;
        }
    }
}

// ---------------- attention: single-term fp16 throughout ----------------
// One block per (win, head), 4 warps x 16 query rows.
// smem: q/k rows 80B stride (64B data), vt/P rows 144B stride (128B data).
#define S_Q   0u
#define S_K   5120u
#define S_VT  10240u     // 32 rows x 144
#define S_P   14848u     // 64 rows x 144
#define S_RCP 24064u     // 64 floats
#define ATTN_SMEM 24320

__global__ __launch_bounds__(128) void attn_kernel(const float* __restrict__ tbl) {
    __shared__ __align__(16) char sm[ATTN_SMEM];
    const uint32_t sb = (uint32_t)__cvta_generic_to_shared(sm);
    float* sRcp = reinterpret_cast<float*>(sm + S_RCP);

    const int bx   = blockIdx.x;
    const int widx = bx >> 4, head = bx & 15;
    const int tid  = threadIdx.x, wid = tid >> 5, lane = tid & 31;
    const int g    = lane >> 2, t4 = lane & 3;

    const __half* qq = g_q16 + (size_t)bx * 2048;
    const __half* kk = g_k16 + (size_t)bx * 2048;
    const __half* vt = g_vt  + (size_t)bx * 2048;

    // ---- stage 12KB via cp.async: q(256 tasks) k(256) vt(256) ----
#pragma unroll
    for (int i = 0; i < 6; i++) {
        int idx = i * 128 + tid;
        if (idx < 512) {
            int arr = idx >> 8;          // 0:q 1:k
            int rem = idx & 255;
            int row = rem >> 2, ch = rem & 3;
            const __half* src = (arr == 0 ? qq : kk) + row * 32 + ch * 8;
            uint32_t base = (arr == 0) ? S_Q : S_K;
            cpa16(sb + base + row * 80 + ch * 16, src);
        } else {
            int rem = idx - 512;
            int r = rem >> 3, ch = rem & 7;
            cpa16(sb + S_VT + r * 144 + ch * 16, vt + r * 64 + ch * 8);
        }
    }
    asm volatile("cp.async.commit_group;\ncp.async.wait_group 0;\n");
    __syncthreads();

    const int r0 = wid * 16;

    // ---- S = Q K^T (single term) ----
    float sacc[8][4];
#pragma unroll
    for (int n = 0; n < 8; n++)
#pragma unroll
        for (int j = 0; j < 4; j++) sacc[n][j] = 0.f;

    const uint32_t aQ = sb + S_Q + (r0 + (lane & 15)) * 80 + ((lane >> 4) & 1) * 16;
    const uint32_t bK = sb + S_K + ((lane & 7) + ((lane >> 4) & 1) * 8) * 80 +
                        ((lane >> 3) & 1) * 16;
#pragma unroll
    for (int kc = 0; kc < 2; kc++) {
        unsigned Aq[4];
        lm4(Aq, aQ + kc * 32);
#pragma unroll
        for (int ng = 0; ng < 4; ng++) {
            unsigned Bv[4];
            lm4(Bv, bK + ng * (16 * 80) + kc * 32);
            mma_f16(sacc[2 * ng + 0], Aq, Bv + 0);
            mma_f16(sacc[2 * ng + 1], Aq, Bv + 2);
        }
    }

    // ---- scale + bias, register softmax ----
    const float scale = 0.17677669529663687f;
    float mx[2] = {-1e30f, -1e30f};
#pragma unroll
    for (int ni = 0; ni < 8; ni++)
#pragma unroll
        for (int j = 0; j < 4; j++) {
            int rg = r0 + g + 8 * (j >> 1);
            int c  = ni * 8 + 2 * t4 + (j & 1);
            int idx = ((rg >> 3) - (c >> 3) + 7) * 15 + ((rg & 7) - (c & 7) + 7);
            float v = sacc[ni][j] * scale + __ldg(tbl + idx * 16 + head);
            sacc[ni][j] = v;
            mx[j >> 1] = fmaxf(mx[j >> 1], v);
        }
#pragma unroll
    for (int h = 0; h < 2; h++) {
        mx[h] = fmaxf(mx[h], __shfl_xor_sync(0xffffffffu, mx[h], 1));
        mx[h] = fmaxf(mx[h], __shfl_xor_sync(0xffffffffu, mx[h], 2));
    }
    float sum[2] = {0.f, 0.f};
#pragma unroll
    for (int ni = 0; ni < 8; ni++)
#pragma unroll
        for (int j = 0; j < 4; j++) {
            float e = __expf(sacc[ni][j] - mx[j >> 1]);
            sacc[ni][j] = e;
            sum[j >> 1] += e;
        }
#pragma unroll
    for (int h = 0; h < 2; h++) {
        sum[h] += __shfl_xor_sync(0xffffffffu, sum[h], 1);
        sum[h] += __shfl_xor_sync(0xffffffffu, sum[h], 2);
    }
    if (t4 == 0) {
        sRcp[r0 + g]     = 1.f / sum[0];
        sRcp[r0 + g + 8] = 1.f / sum[1];
    }

    // ---- store P fp16 into smem ([row][key] A-operand layout) ----
#pragma unroll
    for (int ni = 0; ni < 8; ni++)
#pragma unroll
        for (int jr = 0; jr < 2; jr++) {
            int rg = r0 + g + 8 * jr;
            uint32_t off = (uint32_t)rg * 144u + (uint32_t)(ni * 8 + 2 * t4) * 2u;
            unsigned ph = h2u(__halves2half2(
                __float2half_rn(sacc[ni][2 * jr + 0]),
                __float2half_rn(sacc[ni][2 * jr + 1])));
            asm volatile("st.shared.b32 [%0], %1;" :: "r"(sb + S_P + off), "r"(ph) : "memory");
        }
    __syncwarp();

    // ---- O = P V (single term), B = V^T [dim][key] ----
    float oacc[4][4];
#pragma unroll
    for (int n = 0; n < 4; n++)
#pragma unroll
        for (int j = 0; j < 4; j++) oacc[n][j] = 0.f;

    const uint32_t aP = sb + S_P + (r0 + (lane & 15)) * 144 + ((lane >> 4) & 1) * 16;
    const uint32_t bV = sb + S_VT + ((lane & 7) + ((lane >> 4) & 1) * 8) * 144 +
                        ((lane >> 3) & 1) * 16;
#pragma unroll
    for (int kc = 0; kc < 4; kc++) {
        unsigned Ph[4];
        lm4(Ph, aP + kc * 32);
#pragma unroll
        for (int ng = 0; ng < 2; ng++) {
            unsigned Bv[4];
            lm4(Bv, bV + ng * (16 * 144) + kc * 32);
            mma_f16(oacc[2 * ng + 0], Ph, Bv + 0);
            mma_f16(oacc[2 * ng + 1], Ph, Bv + 2);
        }
    }

    // ---- epilogue: normalize, write single fp16 for proj GEMM ----
#pragma unroll
    for (int ni = 0; ni < 4; ni++)
#pragma unroll
        for (int jr = 0; jr < 2; jr++) {
            int rg = r0 + g + 8 * jr;
            float rcp = sRcp[rg];
            float vx = oacc[ni][2 * jr + 0] * rcp;
            float vy = oacc[ni][2 * jr + 1] * rcp;
            int d = ni * 8 + 2 * t4;
            size_t off = ((size_t)widx * 64 + rg) * 512 + head * 32 + d;
            *reinterpret_cast<__half2*>(g_ao16 + off) =
                __halves2half2(__float2half_rn(vx), __float2half_rn(vy));
        }
}

// ---------------- launch ----------------
extern "C" void kernel_launch(void* const* d_in, const int* in_sizes, int n_in,
                              void* d_out, int out_size) {
    const float* x      = (const float*)d_in[0];
    const float* qkv_w  = (const float*)d_in[1];
    const float* qkv_b  = (const float*)d_in[2];
    const float* proj_w = (const float*)d_in[3];
    const float* proj_b = (const float*)d_in[4];
    const float* tbl    = (const float*)d_in[5];
    float* out = (float*)d_out;

    cudaFuncSetAttribute(gemm_lm<0>, cudaFuncAttributeMaxDynamicSharedMemorySize, GEMM_SMEM);
    cudaFuncSetAttribute(gemm_lm<1>, cudaFuncAttributeMaxDynamicSharedMemorySize, GEMM_SMEM);

    split_x_kernel<<<(NROWS * (CDIM / 4)) / 256, 256>>>(x);
    split_w_kernel<0><<<(1536 * 512) / 256, 256>>>(qkv_w);
    split_w_kernel<1><<<(512 * 512) / 256, 256>>>(proj_w);

    gemm_lm<0><<<NWIN, 256, GEMM_SMEM>>>(qkv_b, nullptr);
    attn_kernel<<<NWIN * NHEADS, 128>>>(tbl);
    gemm_lm<1><<<NWIN, 256, GEMM_SMEM>>>(proj_b, out);
}